// round 1
// baseline (speedup 1.0000x reference)
#include <cuda_runtime.h>
#include <math.h>

#define Bq 2
#define TT 200
#define UU 50
#define DD 256
#define NI 2048
#define VV 5000
#define MM (Bq*TT*UU)   /* 20000 */

#define BM 128
#define BN 128
#define BK 16

// Scratch (sanctioned __device__ globals; no allocations anywhere)
__device__ float g_enc[Bq*TT*NI];            // 2*200*2048
__device__ float g_dec[Bq*UU*NI];            // 2*50*2048
__device__ float g_h[Bq*UU*DD];              // 2*50*256
__device__ float g_joint[(size_t)MM*NI];     // 20000*2048 (~164MB)

// ---------------------------------------------------------------------------
// K1: enc = memory @ W_enc^T + b_enc      [B*T, NI]
// grid (NI/256, B*T), block 256
__global__ void k_enc(const float* __restrict__ mem,
                      const float* __restrict__ W,
                      const float* __restrict__ bias) {
    __shared__ float sx[DD];
    int row = blockIdx.y;
    int j = blockIdx.x * 256 + threadIdx.x;
    sx[threadIdx.x] = mem[row * DD + threadIdx.x];
    __syncthreads();
    const float4* w4 = reinterpret_cast<const float4*>(W + (size_t)j * DD);
    const float4* x4 = reinterpret_cast<const float4*>(sx);
    float acc = bias[j];
#pragma unroll 16
    for (int k = 0; k < DD / 4; k++) {
        float4 w = w4[k], x = x4[k];
        acc += w.x * x.x + w.y * x.y + w.z * x.z + w.w * x.w;
    }
    g_enc[(size_t)row * NI + j] = acc;
}

// ---------------------------------------------------------------------------
// K2: embedding + LSTM. grid B, block 1024 (one thread per gate element)
__global__ void k_lstm(const int* __restrict__ tok,
                       const float* __restrict__ emb,
                       const float* __restrict__ Wih, const float* __restrict__ bih,
                       const float* __restrict__ Whh, const float* __restrict__ bhh) {
    int b = blockIdx.x;
    int tid = threadIdx.x;
    __shared__ float sx[DD], sh[DD], sc[DD], sg[4 * DD];
    if (tid < DD) { sh[tid] = 0.f; sc[tid] = 0.f; }
    const float4* wi4 = reinterpret_cast<const float4*>(Wih + (size_t)tid * DD);
    const float4* wh4 = reinterpret_cast<const float4*>(Whh + (size_t)tid * DD);
    float bsum = bih[tid] + bhh[tid];
    for (int u = 0; u < UU; u++) {
        __syncthreads();
        if (tid < DD) {
            int t = tok[b * UU + u];
            sx[tid] = emb[(size_t)t * DD + tid];
        }
        __syncthreads();
        float acc = bsum;
        const float4* x4 = (const float4*)sx;
        const float4* h4 = (const float4*)sh;
#pragma unroll 8
        for (int k = 0; k < DD / 4; k++) {
            float4 w = wi4[k], x = x4[k];
            acc += w.x * x.x + w.y * x.y + w.z * x.z + w.w * x.w;
        }
#pragma unroll 8
        for (int k = 0; k < DD / 4; k++) {
            float4 w = wh4[k], h = h4[k];
            acc += w.x * h.x + w.y * h.y + w.z * h.z + w.w * h.w;
        }
        sg[tid] = acc;
        __syncthreads();
        if (tid < DD) {
            float ig = 1.f / (1.f + expf(-sg[tid]));
            float fg = 1.f / (1.f + expf(-sg[DD + tid]));
            float gg = tanhf(sg[2 * DD + tid]);
            float og = 1.f / (1.f + expf(-sg[3 * DD + tid]));
            float c = fg * sc[tid] + ig * gg;
            float h = og * tanhf(c);
            sc[tid] = c;
            sh[tid] = h;
            g_h[(b * UU + u) * DD + tid] = h;
        }
    }
}

// ---------------------------------------------------------------------------
// K3: proj + LayerNorm + dec pre-linear. grid B*U, block 256
__global__ void k_proj(const float* __restrict__ Wp, const float* __restrict__ bp,
                       const float* __restrict__ lng, const float* __restrict__ lnb,
                       const float* __restrict__ Wprd, const float* __restrict__ bprd) {
    int row = blockIdx.x;
    int tid = threadIdx.x;
    __shared__ float shh[DD], sy[DD], red[256];
    shh[tid] = g_h[row * DD + tid];
    __syncthreads();
    const float4* h4 = (const float4*)shh;
    {
        const float4* w4 = (const float4*)(Wp + (size_t)tid * DD);
        float p = bp[tid];
#pragma unroll 16
        for (int k = 0; k < DD / 4; k++) {
            float4 w = w4[k], h = h4[k];
            p += w.x * h.x + w.y * h.y + w.z * h.z + w.w * h.w;
        }
        // mean
        red[tid] = p;
        for (int s = 128; s > 0; s >>= 1) { __syncthreads(); if (tid < s) red[tid] += red[tid + s]; }
        __syncthreads();
        float mu = red[0] * (1.f / DD);
        __syncthreads();
        float d = p - mu;
        red[tid] = d * d;
        for (int s = 128; s > 0; s >>= 1) { __syncthreads(); if (tid < s) red[tid] += red[tid + s]; }
        __syncthreads();
        float var = red[0] * (1.f / DD);
        float y = d * rsqrtf(var + 1e-5f) * lng[tid] + lnb[tid];
        sy[tid] = y;
    }
    __syncthreads();
    const float4* y4 = (const float4*)sy;
    for (int j = tid; j < NI; j += 256) {
        const float4* w4 = (const float4*)(Wprd + (size_t)j * DD);
        float acc = bprd[j];
#pragma unroll 16
        for (int k = 0; k < DD / 4; k++) {
            float4 w = w4[k], y = y4[k];
            acc += w.x * y.x + w.y * y.y + w.z * y.z + w.w * y.w;
        }
        g_dec[row * NI + j] = acc;
    }
}

// ---------------------------------------------------------------------------
// K4: joint = tanh(enc[b,t,:] + dec[b,u,:]), materialized fp32. float4 per thread.
__global__ void k_joint() {
    int idx = blockIdx.x * 256 + threadIdx.x;       // float4 index
    int r = idx / (NI / 4);                          // row 0..19999
    int k = (idx % (NI / 4)) * 4;
    int b = r / (TT * UU);
    int rem = r % (TT * UU);
    int t = rem / UU;
    int u = rem % UU;
    float4 e = *(const float4*)&g_enc[(size_t)(b * TT + t) * NI + k];
    float4 d = *(const float4*)&g_dec[(size_t)(b * UU + u) * NI + k];
    float4 o;
    o.x = tanhf(e.x + d.x);
    o.y = tanhf(e.y + d.y);
    o.z = tanhf(e.z + d.z);
    o.w = tanhf(e.w + d.w);
    *(float4*)&g_joint[(size_t)r * NI + k] = o;
}

// ---------------------------------------------------------------------------
// K5: logits = joint @ W_out^T + b_out  (NT SGEMM, both operands K-major)
// 128x128x16 tiles, 256 threads, 8x8 micro-tile
__global__ void k_gemm(const float* __restrict__ Bm,      // W_out [N,K]
                       const float* __restrict__ bias,    // b_out [N]
                       float* __restrict__ C) {           // d_out [M,N]
    __shared__ float As[BK][BM];
    __shared__ float Bs[BK][BN];
    const int tid = threadIdx.x;
    const int bm = blockIdx.y, bn = blockIdx.x;
    const int tx = tid % 16, ty = tid / 16;
    const int lr = tid >> 2;          // 0..63
    const int lc = (tid & 3) << 2;    // 0,4,8,12
    const int M = MM, N = VV, K = NI;

    float acc[8][8];
#pragma unroll
    for (int i = 0; i < 8; i++)
#pragma unroll
        for (int j = 0; j < 8; j++) acc[i][j] = 0.f;

    for (int k0 = 0; k0 < K; k0 += BK) {
#pragma unroll
        for (int i = 0; i < 2; i++) {
            int row = lr + i * 64;
            int gr = bm * BM + row;
            float4 v = make_float4(0.f, 0.f, 0.f, 0.f);
            if (gr < M) v = *(const float4*)&g_joint[(size_t)gr * K + k0 + lc];
            As[lc + 0][row] = v.x; As[lc + 1][row] = v.y;
            As[lc + 2][row] = v.z; As[lc + 3][row] = v.w;
        }
#pragma unroll
        for (int i = 0; i < 2; i++) {
            int row = lr + i * 64;
            int gc = bn * BN + row;
            float4 v = make_float4(0.f, 0.f, 0.f, 0.f);
            if (gc < N) v = *(const float4*)&Bm[(size_t)gc * K + k0 + lc];
            Bs[lc + 0][row] = v.x; Bs[lc + 1][row] = v.y;
            Bs[lc + 2][row] = v.z; Bs[lc + 3][row] = v.w;
        }
        __syncthreads();
#pragma unroll
        for (int k = 0; k < BK; k++) {
            float a[8], b[8];
            *(float4*)&a[0] = *(const float4*)&As[k][ty * 8];
            *(float4*)&a[4] = *(const float4*)&As[k][ty * 8 + 4];
            *(float4*)&b[0] = *(const float4*)&Bs[k][tx * 8];
            *(float4*)&b[4] = *(const float4*)&Bs[k][tx * 8 + 4];
#pragma unroll
            for (int i = 0; i < 8; i++)
#pragma unroll
                for (int j = 0; j < 8; j++)
                    acc[i][j] += a[i] * b[j];
        }
        __syncthreads();
    }
#pragma unroll
    for (int i = 0; i < 8; i++) {
        int gr = bm * BM + ty * 8 + i;
        if (gr >= M) break;
#pragma unroll
        for (int j = 0; j < 8; j++) {
            int gc = bn * BN + tx * 8 + j;
            if (gc < N) C[(size_t)gr * N + gc] = acc[i][j] + bias[gc];
        }
    }
}

// ---------------------------------------------------------------------------
// K6: in-place log_softmax over last dim. grid MM, block 256
__global__ void k_lsm(float* __restrict__ C) {
    const int N = VV;
    int row = blockIdx.x;
    float* p = C + (size_t)row * N;
    __shared__ float red[256];
    int tid = threadIdx.x;

    float m = -1e30f;
    for (int j = tid; j < N; j += 256) m = fmaxf(m, p[j]);
    red[tid] = m;
    for (int s = 128; s > 0; s >>= 1) { __syncthreads(); if (tid < s) red[tid] = fmaxf(red[tid], red[tid + s]); }
    __syncthreads();
    m = red[0];
    __syncthreads();

    float sum = 0.f;
    for (int j = tid; j < N; j += 256) sum += expf(p[j] - m);
    red[tid] = sum;
    for (int s = 128; s > 0; s >>= 1) { __syncthreads(); if (tid < s) red[tid] += red[tid + s]; }
    __syncthreads();
    float lse = m + logf(red[0]);

    for (int j = tid; j < N; j += 256) p[j] = p[j] - lse;
}

// ---------------------------------------------------------------------------
extern "C" void kernel_launch(void* const* d_in, const int* in_sizes, int n_in,
                              void* d_out, int out_size) {
    const float* memory = (const float*)d_in[0];
    const int*   ys     = (const int*)d_in[1];
    // d_in[2] = ys_in_lens: unused by the reference
    const float* emb    = (const float*)d_in[3];
    const float* Wih    = (const float*)d_in[4];
    const float* bih    = (const float*)d_in[5];
    const float* Whh    = (const float*)d_in[6];
    const float* bhh    = (const float*)d_in[7];
    const float* Wproj  = (const float*)d_in[8];
    const float* bproj  = (const float*)d_in[9];
    const float* lng    = (const float*)d_in[10];
    const float* lnb    = (const float*)d_in[11];
    const float* Wenc   = (const float*)d_in[12];
    const float* benc   = (const float*)d_in[13];
    const float* Wprd   = (const float*)d_in[14];
    const float* bprd   = (const float*)d_in[15];
    const float* Wout   = (const float*)d_in[16];
    const float* bout   = (const float*)d_in[17];
    float* out = (float*)d_out;

    dim3 ge(NI / 256, Bq * TT);
    k_enc<<<ge, 256>>>(memory, Wenc, benc);
    k_lstm<<<Bq, 1024>>>(ys, emb, Wih, bih, Whh, bhh);
    k_proj<<<Bq * UU, 256>>>(Wproj, bproj, lng, lnb, Wprd, bprd);
    k_joint<<<(MM * (NI / 4)) / 256, 256>>>();
    dim3 gg((VV + BN - 1) / BN, (MM + BM - 1) / BM);
    k_gemm<<<gg, 256>>>(Wout, bout, out);
    k_lsm<<<MM, 256>>>(out);
}

// round 4
// speedup vs baseline: 2.4835x; 2.4835x over previous
#include <cuda_runtime.h>
#include <cuda_bf16.h>
#include <cstdint>
#include <math.h>

#define Bq 2
#define TT 200
#define UU 50
#define DD 256
#define NI 2048
#define VV 5000
#define MM (Bq*TT*UU)   /* 20000 */

#define SSTR 40          /* padded smem row stride in bf16 */

// Scratch (__device__ globals; no allocations anywhere)
__device__ float g_enc[Bq*TT*NI];
__device__ float g_dec[Bq*UU*NI];
__device__ float g_h[Bq*UU*DD];
__device__ __nv_bfloat16 g_jointh[(size_t)MM*NI];   // 82MB bf16
__device__ __nv_bfloat16 g_woutb[(size_t)VV*NI];    // 20MB bf16

__device__ __forceinline__ uint32_t smem_u32(const void* p) {
    uint32_t a;
    asm("{ .reg .u64 t; cvta.to.shared.u64 t, %1; cvt.u32.u64 %0, t; }" : "=r"(a) : "l"(p));
    return a;
}

// ---------------------------------------------------------------------------
// K1: enc = memory @ W_enc^T + b_enc
__global__ void k_enc(const float* __restrict__ mem,
                      const float* __restrict__ W,
                      const float* __restrict__ bias) {
    __shared__ float sx[DD];
    int row = blockIdx.y;
    int j = blockIdx.x * 256 + threadIdx.x;
    sx[threadIdx.x] = mem[row * DD + threadIdx.x];
    __syncthreads();
    const float4* w4 = reinterpret_cast<const float4*>(W + (size_t)j * DD);
    const float4* x4 = reinterpret_cast<const float4*>(sx);
    float acc = bias[j];
#pragma unroll 16
    for (int k = 0; k < DD / 4; k++) {
        float4 w = w4[k], x = x4[k];
        acc += w.x * x.x + w.y * x.y + w.z * x.z + w.w * x.w;
    }
    g_enc[(size_t)row * NI + j] = acc;
}

// ---------------------------------------------------------------------------
// K2: embedding + LSTM
__global__ void k_lstm(const int* __restrict__ tok,
                       const float* __restrict__ emb,
                       const float* __restrict__ Wih, const float* __restrict__ bih,
                       const float* __restrict__ Whh, const float* __restrict__ bhh) {
    int b = blockIdx.x;
    int tid = threadIdx.x;
    __shared__ float sx[DD], sh[DD], sc[DD], sg[4 * DD];
    if (tid < DD) { sh[tid] = 0.f; sc[tid] = 0.f; }
    const float4* wi4 = reinterpret_cast<const float4*>(Wih + (size_t)tid * DD);
    const float4* wh4 = reinterpret_cast<const float4*>(Whh + (size_t)tid * DD);
    float bsum = bih[tid] + bhh[tid];
    for (int u = 0; u < UU; u++) {
        __syncthreads();
        if (tid < DD) {
            int t = tok[b * UU + u];
            sx[tid] = emb[(size_t)t * DD + tid];
        }
        __syncthreads();
        float acc = bsum;
        const float4* x4 = (const float4*)sx;
        const float4* h4 = (const float4*)sh;
#pragma unroll 8
        for (int k = 0; k < DD / 4; k++) {
            float4 w = wi4[k], x = x4[k];
            acc += w.x * x.x + w.y * x.y + w.z * x.z + w.w * x.w;
        }
#pragma unroll 8
        for (int k = 0; k < DD / 4; k++) {
            float4 w = wh4[k], h = h4[k];
            acc += w.x * h.x + w.y * h.y + w.z * h.z + w.w * h.w;
        }
        sg[tid] = acc;
        __syncthreads();
        if (tid < DD) {
            float ig = 1.f / (1.f + expf(-sg[tid]));
            float fg = 1.f / (1.f + expf(-sg[DD + tid]));
            float gg = tanhf(sg[2 * DD + tid]);
            float og = 1.f / (1.f + expf(-sg[3 * DD + tid]));
            float c = fg * sc[tid] + ig * gg;
            float h = og * tanhf(c);
            sc[tid] = c;
            sh[tid] = h;
            g_h[(b * UU + u) * DD + tid] = h;
        }
    }
}

// ---------------------------------------------------------------------------
// K3: proj + LayerNorm + dec pre-linear
__global__ void k_proj(const float* __restrict__ Wp, const float* __restrict__ bp,
                       const float* __restrict__ lng, const float* __restrict__ lnb,
                       const float* __restrict__ Wprd, const float* __restrict__ bprd) {
    int row = blockIdx.x;
    int tid = threadIdx.x;
    __shared__ float shh[DD], sy[DD], red[256];
    shh[tid] = g_h[row * DD + tid];
    __syncthreads();
    {
        const float4* h4 = (const float4*)shh;
        const float4* w4 = (const float4*)(Wp + (size_t)tid * DD);
        float p = bp[tid];
#pragma unroll 16
        for (int k = 0; k < DD / 4; k++) {
            float4 w = w4[k], h = h4[k];
            p += w.x * h.x + w.y * h.y + w.z * h.z + w.w * h.w;
        }
        red[tid] = p;
        for (int s = 128; s > 0; s >>= 1) { __syncthreads(); if (tid < s) red[tid] += red[tid + s]; }
        __syncthreads();
        float mu = red[0] * (1.f / DD);
        __syncthreads();
        float d = p - mu;
        red[tid] = d * d;
        for (int s = 128; s > 0; s >>= 1) { __syncthreads(); if (tid < s) red[tid] += red[tid + s]; }
        __syncthreads();
        float var = red[0] * (1.f / DD);
        float y = d * rsqrtf(var + 1e-5f) * lng[tid] + lnb[tid];
        sy[tid] = y;
    }
    __syncthreads();
    const float4* y4 = (const float4*)sy;
    for (int j = tid; j < NI; j += 256) {
        const float4* w4 = (const float4*)(Wprd + (size_t)j * DD);
        float acc = bprd[j];
#pragma unroll 16
        for (int k = 0; k < DD / 4; k++) {
            float4 w = w4[k], y = y4[k];
            acc += w.x * y.x + w.y * y.y + w.z * y.z + w.w * y.w;
        }
        g_dec[row * NI + j] = acc;
    }
}

// ---------------------------------------------------------------------------
// K4: joint = tanh(enc + dec) -> bf16
__global__ void k_joint() {
    int idx = blockIdx.x * 256 + threadIdx.x;       // float4 index
    int r = idx / (NI / 4);
    int k = (idx % (NI / 4)) * 4;
    int b = r / (TT * UU);
    int rem = r % (TT * UU);
    int t = rem / UU;
    int u = rem % UU;
    float4 e = *(const float4*)&g_enc[(size_t)(b * TT + t) * NI + k];
    float4 d = *(const float4*)&g_dec[(size_t)(b * UU + u) * NI + k];
    __nv_bfloat162 lo = __floats2bfloat162_rn(tanhf(e.x + d.x), tanhf(e.y + d.y));
    __nv_bfloat162 hi = __floats2bfloat162_rn(tanhf(e.z + d.z), tanhf(e.w + d.w));
    uint2 pk;
    pk.x = *(uint32_t*)&lo;
    pk.y = *(uint32_t*)&hi;
    *(uint2*)&g_jointh[(size_t)r * NI + k] = pk;
}

// ---------------------------------------------------------------------------
// K4b: W_out -> bf16
__global__ void k_wconv(const float* __restrict__ W) {
    size_t i = ((size_t)blockIdx.x * 256 + threadIdx.x) * 4;
    float4 v = *(const float4*)(W + i);
    __nv_bfloat162 lo = __floats2bfloat162_rn(v.x, v.y);
    __nv_bfloat162 hi = __floats2bfloat162_rn(v.z, v.w);
    uint2 pk;
    pk.x = *(uint32_t*)&lo;
    pk.y = *(uint32_t*)&hi;
    *(uint2*)&g_woutb[i] = pk;
}

// ---------------------------------------------------------------------------
// K5: logits = joint @ W_out^T + b_out via mma.sync bf16 (HMMA)
// 128x128x32 CTA tile, 8 warps, warp = 64x32, double-buffered cp.async
#define NIT (NI/32)   /* 64 */

__device__ __forceinline__ void cp16(uint32_t dst, const void* src, int sz) {
    asm volatile("cp.async.cg.shared.global [%0], [%1], 16, %2;"
                 :: "r"(dst), "l"(src), "r"(sz));
}

__global__ void __launch_bounds__(256) k_gemm_hmma(const float* __restrict__ bias,
                                                  float* __restrict__ C) {
    __shared__ __nv_bfloat16 As[2][128 * SSTR];
    __shared__ __nv_bfloat16 Bs[2][128 * SSTR];

    const int tid = threadIdx.x;
    const int wid = tid >> 5, lid = tid & 31;
    const int wm = wid >> 2, wn = wid & 3;       // warp grid 2x4
    const int g = lid >> 2, t = lid & 3;         // mma lane decomposition
    const int bm = blockIdx.y, bn = blockIdx.x;

    float acc[4][4][4];
#pragma unroll
    for (int i = 0; i < 4; i++)
#pragma unroll
        for (int j = 0; j < 4; j++)
#pragma unroll
            for (int k = 0; k < 4; k++) acc[i][j][k] = 0.f;

    const int row0 = tid >> 2;          // 0..63  (two rows per thread: row0, row0+64)
    const int ch = tid & 3;             // 16B chunk within 64B row

    // prologue: load tile 0 into buf 0
#pragma unroll
    for (int half = 0; half < 2; half++) {
        int row = row0 + half * 64;
        int gr = bm * 128 + row;
        int grc = gr < MM ? gr : MM - 1;
        cp16(smem_u32(&As[0][row * SSTR + ch * 8]),
             g_jointh + (size_t)grc * NI + ch * 8, gr < MM ? 16 : 0);
        int gc = bn * 128 + row;
        int gcc = gc < VV ? gc : VV - 1;
        cp16(smem_u32(&Bs[0][row * SSTR + ch * 8]),
             g_woutb + (size_t)gcc * NI + ch * 8, gc < VV ? 16 : 0);
    }
    asm volatile("cp.async.commit_group;");

    for (int it = 0; it < NIT; it++) {
        int buf = it & 1;
        if (it + 1 < NIT) {
            int ck = (it + 1) * 32;
#pragma unroll
            for (int half = 0; half < 2; half++) {
                int row = row0 + half * 64;
                int gr = bm * 128 + row;
                int grc = gr < MM ? gr : MM - 1;
                cp16(smem_u32(&As[buf ^ 1][row * SSTR + ch * 8]),
                     g_jointh + (size_t)grc * NI + ck + ch * 8, gr < MM ? 16 : 0);
                int gc = bn * 128 + row;
                int gcc = gc < VV ? gc : VV - 1;
                cp16(smem_u32(&Bs[buf ^ 1][row * SSTR + ch * 8]),
                     g_woutb + (size_t)gcc * NI + ck + ch * 8, gc < VV ? 16 : 0);
            }
            asm volatile("cp.async.commit_group;");
            asm volatile("cp.async.wait_group 1;");
        } else {
            asm volatile("cp.async.wait_group 0;");
        }
        __syncthreads();

        const __nv_bfloat16* as = As[buf];
        const __nv_bfloat16* bs = Bs[buf];
#pragma unroll
        for (int ks = 0; ks < 2; ks++) {
            const int kk = ks * 16;
            uint32_t ar[4][4], br[4][2];
#pragma unroll
            for (int mi = 0; mi < 4; mi++) {
                int R = wm * 64 + mi * 16;
                ar[mi][0] = *(const uint32_t*)(as + (R + g) * SSTR + kk + 2 * t);
                ar[mi][1] = *(const uint32_t*)(as + (R + g + 8) * SSTR + kk + 2 * t);
                ar[mi][2] = *(const uint32_t*)(as + (R + g) * SSTR + kk + 2 * t + 8);
                ar[mi][3] = *(const uint32_t*)(as + (R + g + 8) * SSTR + kk + 2 * t + 8);
            }
#pragma unroll
            for (int ni = 0; ni < 4; ni++) {
                int Cc = wn * 32 + ni * 8;
                br[ni][0] = *(const uint32_t*)(bs + (Cc + g) * SSTR + kk + 2 * t);
                br[ni][1] = *(const uint32_t*)(bs + (Cc + g) * SSTR + kk + 2 * t + 8);
            }
#pragma unroll
            for (int mi = 0; mi < 4; mi++)
#pragma unroll
                for (int ni = 0; ni < 4; ni++)
                    asm volatile(
                        "mma.sync.aligned.m16n8k16.row.col.f32.bf16.bf16.f32 "
                        "{%0,%1,%2,%3}, {%4,%5,%6,%7}, {%8,%9}, {%0,%1,%2,%3};"
                        : "+f"(acc[mi][ni][0]), "+f"(acc[mi][ni][1]),
                          "+f"(acc[mi][ni][2]), "+f"(acc[mi][ni][3])
                        : "r"(ar[mi][0]), "r"(ar[mi][1]), "r"(ar[mi][2]), "r"(ar[mi][3]),
                          "r"(br[ni][0]), "r"(br[ni][1]));
        }
        __syncthreads();
    }

    // epilogue: bias add + guarded store
#pragma unroll
    for (int mi = 0; mi < 4; mi++) {
        int gr0 = bm * 128 + wm * 64 + mi * 16 + g;
#pragma unroll
        for (int ni = 0; ni < 4; ni++) {
            int gc0 = bn * 128 + wn * 32 + ni * 8 + 2 * t;
            float b0 = (gc0 < VV) ? __ldg(&bias[gc0]) : 0.f;
            float b1 = (gc0 + 1 < VV) ? __ldg(&bias[gc0 + 1]) : 0.f;
            if (gr0 < MM) {
                if (gc0 < VV)     C[(size_t)gr0 * VV + gc0]     = acc[mi][ni][0] + b0;
                if (gc0 + 1 < VV) C[(size_t)gr0 * VV + gc0 + 1] = acc[mi][ni][1] + b1;
            }
            if (gr0 + 8 < MM) {
                if (gc0 < VV)     C[(size_t)(gr0 + 8) * VV + gc0]     = acc[mi][ni][2] + b0;
                if (gc0 + 1 < VV) C[(size_t)(gr0 + 8) * VV + gc0 + 1] = acc[mi][ni][3] + b1;
            }
        }
    }
}

// ---------------------------------------------------------------------------
// K6: in-place log_softmax
__global__ void k_lsm(float* __restrict__ C) {
    const int N = VV;
    int row = blockIdx.x;
    float* p = C + (size_t)row * N;
    __shared__ float red[256];
    int tid = threadIdx.x;

    float m = -1e30f;
    for (int j = tid; j < N; j += 256) m = fmaxf(m, p[j]);
    red[tid] = m;
    for (int s = 128; s > 0; s >>= 1) { __syncthreads(); if (tid < s) red[tid] = fmaxf(red[tid], red[tid + s]); }
    __syncthreads();
    m = red[0];
    __syncthreads();

    float sum = 0.f;
    for (int j = tid; j < N; j += 256) sum += expf(p[j] - m);
    red[tid] = sum;
    for (int s = 128; s > 0; s >>= 1) { __syncthreads(); if (tid < s) red[tid] += red[tid + s]; }
    __syncthreads();
    float lse = m + logf(red[0]);

    for (int j = tid; j < N; j += 256) p[j] = p[j] - lse;
}

// ---------------------------------------------------------------------------
extern "C" void kernel_launch(void* const* d_in, const int* in_sizes, int n_in,
                              void* d_out, int out_size) {
    const float* memory = (const float*)d_in[0];
    const int*   ys     = (const int*)d_in[1];
    const float* emb    = (const float*)d_in[3];
    const float* Wih    = (const float*)d_in[4];
    const float* bih    = (const float*)d_in[5];
    const float* Whh    = (const float*)d_in[6];
    const float* bhh    = (const float*)d_in[7];
    const float* Wproj  = (const float*)d_in[8];
    const float* bproj  = (const float*)d_in[9];
    const float* lng    = (const float*)d_in[10];
    const float* lnb    = (const float*)d_in[11];
    const float* Wenc   = (const float*)d_in[12];
    const float* benc   = (const float*)d_in[13];
    const float* Wprd   = (const float*)d_in[14];
    const float* bprd   = (const float*)d_in[15];
    const float* Wout   = (const float*)d_in[16];
    const float* bout   = (const float*)d_in[17];
    float* out = (float*)d_out;

    dim3 ge(NI / 256, Bq * TT);
    k_enc<<<ge, 256>>>(memory, Wenc, benc);
    k_lstm<<<Bq, 1024>>>(ys, emb, Wih, bih, Whh, bhh);
    k_proj<<<Bq * UU, 256>>>(Wproj, bproj, lng, lnb, Wprd, bprd);
    k_joint<<<(MM * (NI / 4)) / 256, 256>>>();
    k_wconv<<<(VV * NI) / 4 / 256, 256>>>(Wout);
    dim3 gg((VV + 127) / 128, (MM + 127) / 128);
    k_gemm_hmma<<<gg, 256>>>(bout, out);
    k_lsm<<<MM, 256>>>(out);
}

// round 5
// speedup vs baseline: 4.5957x; 1.8505x over previous
#include <cuda_runtime.h>
#include <cuda_bf16.h>
#include <cstdint>
#include <math.h>

#define Bq 2
#define TT 200
#define UU 50
#define DD 256
#define NI 2048
#define VV 5000
#define MM (Bq*TT*UU)   /* 20000 */

#define SSTR 40          /* padded smem row stride in bf16 */

// Scratch (__device__ globals; no allocations anywhere)
__device__ float g_enc[Bq*TT*NI];
__device__ float g_dec[Bq*UU*NI];
__device__ float g_h[Bq*UU*DD];
__device__ float g_gx[Bq*UU*4*DD];                  // precomputed input gates
__device__ __nv_bfloat16 g_whhb[4*DD*DD];           // W_hh bf16
__device__ __nv_bfloat16 g_jointh[(size_t)MM*NI];   // 82MB bf16
__device__ __nv_bfloat16 g_woutb[(size_t)VV*NI];    // 20MB bf16

__device__ __forceinline__ uint32_t smem_u32(const void* p) {
    uint32_t a;
    asm("{ .reg .u64 t; cvta.to.shared.u64 t, %1; cvt.u32.u64 %0, t; }" : "=r"(a) : "l"(p));
    return a;
}

// ---------------------------------------------------------------------------
// K1: enc = memory @ W_enc^T + b_enc
__global__ void k_enc(const float* __restrict__ mem,
                      const float* __restrict__ W,
                      const float* __restrict__ bias) {
    __shared__ float sx[DD];
    int row = blockIdx.y;
    int j = blockIdx.x * 256 + threadIdx.x;
    sx[threadIdx.x] = mem[row * DD + threadIdx.x];
    __syncthreads();
    const float4* w4 = reinterpret_cast<const float4*>(W + (size_t)j * DD);
    const float4* x4 = reinterpret_cast<const float4*>(sx);
    float acc = bias[j];
#pragma unroll 16
    for (int k = 0; k < DD / 4; k++) {
        float4 w = w4[k], x = x4[k];
        acc += w.x * x.x + w.y * x.y + w.z * x.z + w.w * x.w;
    }
    g_enc[(size_t)row * NI + j] = acc;
}

// ---------------------------------------------------------------------------
// K2a: gx[row, j] = emb[tok[row]] . W_ih[j] + b_ih[j] + b_hh[j]
__global__ void k_gx(const int* __restrict__ tok,
                     const float* __restrict__ emb,
                     const float* __restrict__ Wih, const float* __restrict__ bih,
                     const float* __restrict__ bhh) {
    __shared__ float sx[DD];
    int row = blockIdx.y;                  // b*UU + u
    int j = blockIdx.x * 256 + threadIdx.x;
    if (threadIdx.x < DD) {
        int t = tok[row];
        sx[threadIdx.x] = emb[(size_t)t * DD + threadIdx.x];
    }
    __syncthreads();
    const float4* w4 = (const float4*)(Wih + (size_t)j * DD);
    const float4* x4 = (const float4*)sx;
    float acc = bih[j] + bhh[j];
#pragma unroll 16
    for (int k = 0; k < DD / 4; k++) {
        float4 w = w4[k], x = x4[k];
        acc += w.x * x.x + w.y * x.y + w.z * x.z + w.w * x.w;
    }
    g_gx[(size_t)row * (4 * DD) + j] = acc;
}

// K2b: W_hh -> bf16
__global__ void k_whconv(const float* __restrict__ W) {
    size_t i = ((size_t)blockIdx.x * 256 + threadIdx.x) * 4;
    float4 v = *(const float4*)(W + i);
    __nv_bfloat162 lo = __floats2bfloat162_rn(v.x, v.y);
    __nv_bfloat162 hi = __floats2bfloat162_rn(v.z, v.w);
    uint2 pk;
    pk.x = *(uint32_t*)&lo;
    pk.y = *(uint32_t*)&hi;
    *(uint2*)&g_whhb[i] = pk;
}

// K2c: recurrent LSTM with bf16 W_hh, precomputed gx
__global__ void k_lstm_r() {
    int b = blockIdx.x;
    int tid = threadIdx.x;
    __shared__ float sh[DD], sc[DD], sg[4 * DD];
    if (tid < DD) { sh[tid] = 0.f; sc[tid] = 0.f; }
    const uint4* w = (const uint4*)(g_whhb + (size_t)tid * DD);   // 32 x uint4 (8 bf16)
    const float4* sh4 = (const float4*)sh;
    __syncthreads();
    for (int u = 0; u < UU; u++) {
        float acc = g_gx[(size_t)(b * UU + u) * (4 * DD) + tid];
#pragma unroll
        for (int k = 0; k < 32; k++) {
            uint4 q = w[k];
            float4 ha = sh4[2 * k], hb = sh4[2 * k + 1];
            float2 c0 = __bfloat1622float2(*(const __nv_bfloat162*)&q.x);
            float2 c1 = __bfloat1622float2(*(const __nv_bfloat162*)&q.y);
            float2 c2 = __bfloat1622float2(*(const __nv_bfloat162*)&q.z);
            float2 c3 = __bfloat1622float2(*(const __nv_bfloat162*)&q.w);
            acc += c0.x * ha.x + c0.y * ha.y + c1.x * ha.z + c1.y * ha.w;
            acc += c2.x * hb.x + c2.y * hb.y + c3.x * hb.z + c3.y * hb.w;
        }
        sg[tid] = acc;
        __syncthreads();
        if (tid < DD) {
            float ig = 1.f / (1.f + expf(-sg[tid]));
            float fg = 1.f / (1.f + expf(-sg[DD + tid]));
            float gg = tanhf(sg[2 * DD + tid]);
            float og = 1.f / (1.f + expf(-sg[3 * DD + tid]));
            float c = fg * sc[tid] + ig * gg;
            float h = og * tanhf(c);
            sc[tid] = c;
            sh[tid] = h;
            g_h[(b * UU + u) * DD + tid] = h;
        }
        __syncthreads();
    }
}

// ---------------------------------------------------------------------------
// K3: proj + LayerNorm + dec pre-linear
__global__ void k_proj(const float* __restrict__ Wp, const float* __restrict__ bp,
                       const float* __restrict__ lng, const float* __restrict__ lnb,
                       const float* __restrict__ Wprd, const float* __restrict__ bprd) {
    int row = blockIdx.x;
    int tid = threadIdx.x;
    __shared__ float shh[DD], sy[DD], red[256];
    shh[tid] = g_h[row * DD + tid];
    __syncthreads();
    {
        const float4* h4 = (const float4*)shh;
        const float4* w4 = (const float4*)(Wp + (size_t)tid * DD);
        float p = bp[tid];
#pragma unroll 16
        for (int k = 0; k < DD / 4; k++) {
            float4 w = w4[k], h = h4[k];
            p += w.x * h.x + w.y * h.y + w.z * h.z + w.w * h.w;
        }
        red[tid] = p;
        for (int s = 128; s > 0; s >>= 1) { __syncthreads(); if (tid < s) red[tid] += red[tid + s]; }
        __syncthreads();
        float mu = red[0] * (1.f / DD);
        __syncthreads();
        float d = p - mu;
        red[tid] = d * d;
        for (int s = 128; s > 0; s >>= 1) { __syncthreads(); if (tid < s) red[tid] += red[tid + s]; }
        __syncthreads();
        float var = red[0] * (1.f / DD);
        float y = d * rsqrtf(var + 1e-5f) * lng[tid] + lnb[tid];
        sy[tid] = y;
    }
    __syncthreads();
    const float4* y4 = (const float4*)sy;
    for (int j = tid; j < NI; j += 256) {
        const float4* w4 = (const float4*)(Wprd + (size_t)j * DD);
        float acc = bprd[j];
#pragma unroll 16
        for (int k = 0; k < DD / 4; k++) {
            float4 w = w4[k], y = y4[k];
            acc += w.x * y.x + w.y * y.y + w.z * y.z + w.w * y.w;
        }
        g_dec[row * NI + j] = acc;
    }
}

// ---------------------------------------------------------------------------
// K4: joint = tanh(enc + dec) -> bf16
__global__ void k_joint() {
    int idx = blockIdx.x * 256 + threadIdx.x;       // float4 index
    int r = idx / (NI / 4);
    int k = (idx % (NI / 4)) * 4;
    int b = r / (TT * UU);
    int rem = r % (TT * UU);
    int t = rem / UU;
    int u = rem % UU;
    float4 e = *(const float4*)&g_enc[(size_t)(b * TT + t) * NI + k];
    float4 d = *(const float4*)&g_dec[(size_t)(b * UU + u) * NI + k];
    __nv_bfloat162 lo = __floats2bfloat162_rn(tanhf(e.x + d.x), tanhf(e.y + d.y));
    __nv_bfloat162 hi = __floats2bfloat162_rn(tanhf(e.z + d.z), tanhf(e.w + d.w));
    uint2 pk;
    pk.x = *(uint32_t*)&lo;
    pk.y = *(uint32_t*)&hi;
    *(uint2*)&g_jointh[(size_t)r * NI + k] = pk;
}

// ---------------------------------------------------------------------------
// K4b: W_out -> bf16
__global__ void k_wconv(const float* __restrict__ W) {
    size_t i = ((size_t)blockIdx.x * 256 + threadIdx.x) * 4;
    float4 v = *(const float4*)(W + i);
    __nv_bfloat162 lo = __floats2bfloat162_rn(v.x, v.y);
    __nv_bfloat162 hi = __floats2bfloat162_rn(v.z, v.w);
    uint2 pk;
    pk.x = *(uint32_t*)&lo;
    pk.y = *(uint32_t*)&hi;
    *(uint2*)&g_woutb[i] = pk;
}

// ---------------------------------------------------------------------------
// K5: logits = joint @ W_out^T + b_out via mma.sync bf16 + ldmatrix
// 128x128x32 CTA tile, 8 warps (2x4), warp = 64x32, double-buffered cp.async
#define NIT (NI/32)   /* 64 */

__device__ __forceinline__ void cp16(uint32_t dst, const void* src, int sz) {
    asm volatile("cp.async.cg.shared.global [%0], [%1], 16, %2;"
                 :: "r"(dst), "l"(src), "r"(sz));
}

#define LDM_X4(r0, r1, r2, r3, a) \
    asm volatile("ldmatrix.sync.aligned.m8n8.x4.shared.b16 {%0,%1,%2,%3}, [%4];" \
                 : "=r"(r0), "=r"(r1), "=r"(r2), "=r"(r3) : "r"(a))

__global__ void __launch_bounds__(256, 2) k_gemm_hmma(const float* __restrict__ bias,
                                                      float* __restrict__ C) {
    __shared__ __nv_bfloat16 As[2][128 * SSTR];   // 10240B each
    __shared__ __nv_bfloat16 Bs[2][128 * SSTR];

    const int tid = threadIdx.x;
    const int wid = tid >> 5, lid = tid & 31;
    const int wm = wid >> 2, wn = wid & 3;       // warp grid 2x4
    const int g = lid >> 2, t = lid & 3;         // mma lane decomposition
    const int bm = blockIdx.y, bn = blockIdx.x;

    // ldmatrix per-lane tile offsets (elements): quad q = lid>>3, r = lid&7
    const int lq = lid >> 3, lr_ = lid & 7;
    const int ld_row = ((lq & 1) << 3) + lr_;    // 0..15
    const int ld_col = (lq >> 1) << 3;           // 0 or 8
    int aoff[4], boff[2];
#pragma unroll
    for (int mi = 0; mi < 4; mi++)
        aoff[mi] = (wm * 64 + mi * 16 + ld_row) * SSTR + ld_col;
#pragma unroll
    for (int p = 0; p < 2; p++)
        boff[p] = (wn * 32 + p * 16 + ld_row) * SSTR + ld_col;

    const uint32_t asb0 = smem_u32(&As[0][0]), asb1 = smem_u32(&As[1][0]);
    const uint32_t bsb0 = smem_u32(&Bs[0][0]), bsb1 = smem_u32(&Bs[1][0]);

    float acc[4][4][4];
#pragma unroll
    for (int i = 0; i < 4; i++)
#pragma unroll
        for (int j = 0; j < 4; j++)
#pragma unroll
            for (int k = 0; k < 4; k++) acc[i][j][k] = 0.f;

    const int row0 = tid >> 2;          // 0..63  (two rows: row0, row0+64)
    const int ch = tid & 3;             // 16B chunk within 64B row

    // prologue: load tile 0 into buf 0
#pragma unroll
    for (int half = 0; half < 2; half++) {
        int row = row0 + half * 64;
        int gr = bm * 128 + row;
        int grc = gr < MM ? gr : MM - 1;
        cp16(smem_u32(&As[0][row * SSTR + ch * 8]),
             g_jointh + (size_t)grc * NI + ch * 8, gr < MM ? 16 : 0);
        int gc = bn * 128 + row;
        int gcc = gc < VV ? gc : VV - 1;
        cp16(smem_u32(&Bs[0][row * SSTR + ch * 8]),
             g_woutb + (size_t)gcc * NI + ch * 8, gc < VV ? 16 : 0);
    }
    asm volatile("cp.async.commit_group;");

    for (int it = 0; it < NIT; it++) {
        int buf = it & 1;
        if (it + 1 < NIT) {
            int ck = (it + 1) * 32;
#pragma unroll
            for (int half = 0; half < 2; half++) {
                int row = row0 + half * 64;
                int gr = bm * 128 + row;
                int grc = gr < MM ? gr : MM - 1;
                cp16(smem_u32(&As[buf ^ 1][row * SSTR + ch * 8]),
                     g_jointh + (size_t)grc * NI + ck + ch * 8, gr < MM ? 16 : 0);
                int gc = bn * 128 + row;
                int gcc = gc < VV ? gc : VV - 1;
                cp16(smem_u32(&Bs[buf ^ 1][row * SSTR + ch * 8]),
                     g_woutb + (size_t)gcc * NI + ck + ch * 8, gc < VV ? 16 : 0);
            }
            asm volatile("cp.async.commit_group;");
            asm volatile("cp.async.wait_group 1;");
        } else {
            asm volatile("cp.async.wait_group 0;");
        }
        __syncthreads();

        const uint32_t asb = buf ? asb1 : asb0;
        const uint32_t bsb = buf ? bsb1 : bsb0;
#pragma unroll
        for (int ks = 0; ks < 2; ks++) {
            const int kk = ks * 16;
            uint32_t ar[4][4], br[2][4];
#pragma unroll
            for (int mi = 0; mi < 4; mi++)
                LDM_X4(ar[mi][0], ar[mi][1], ar[mi][2], ar[mi][3],
                       asb + ((aoff[mi] + kk) << 1));
#pragma unroll
            for (int p = 0; p < 2; p++)
                LDM_X4(br[p][0], br[p][1], br[p][2], br[p][3],
                       bsb + ((boff[p] + kk) << 1));
#pragma unroll
            for (int mi = 0; mi < 4; mi++) {
#pragma unroll
                for (int p = 0; p < 2; p++) {
                    asm volatile(
                        "mma.sync.aligned.m16n8k16.row.col.f32.bf16.bf16.f32 "
                        "{%0,%1,%2,%3}, {%4,%5,%6,%7}, {%8,%9}, {%0,%1,%2,%3};"
                        : "+f"(acc[mi][2 * p][0]), "+f"(acc[mi][2 * p][1]),
                          "+f"(acc[mi][2 * p][2]), "+f"(acc[mi][2 * p][3])
                        : "r"(ar[mi][0]), "r"(ar[mi][1]), "r"(ar[mi][2]), "r"(ar[mi][3]),
                          "r"(br[p][0]), "r"(br[p][2]));
                    asm volatile(
                        "mma.sync.aligned.m16n8k16.row.col.f32.bf16.bf16.f32 "
                        "{%0,%1,%2,%3}, {%4,%5,%6,%7}, {%8,%9}, {%0,%1,%2,%3};"
                        : "+f"(acc[mi][2 * p + 1][0]), "+f"(acc[mi][2 * p + 1][1]),
                          "+f"(acc[mi][2 * p + 1][2]), "+f"(acc[mi][2 * p + 1][3])
                        : "r"(ar[mi][0]), "r"(ar[mi][1]), "r"(ar[mi][2]), "r"(ar[mi][3]),
                          "r"(br[p][1]), "r"(br[p][3]));
                }
            }
        }
        __syncthreads();
    }

    // epilogue: bias add + guarded store
#pragma unroll
    for (int mi = 0; mi < 4; mi++) {
        int gr0 = bm * 128 + wm * 64 + mi * 16 + g;
#pragma unroll
        for (int ni = 0; ni < 4; ni++) {
            int gc0 = bn * 128 + wn * 32 + ni * 8 + 2 * t;
            float b0 = (gc0 < VV) ? __ldg(&bias[gc0]) : 0.f;
            float b1 = (gc0 + 1 < VV) ? __ldg(&bias[gc0 + 1]) : 0.f;
            if (gr0 < MM) {
                if (gc0 < VV)     C[(size_t)gr0 * VV + gc0]     = acc[mi][ni][0] + b0;
                if (gc0 + 1 < VV) C[(size_t)gr0 * VV + gc0 + 1] = acc[mi][ni][1] + b1;
            }
            if (gr0 + 8 < MM) {
                if (gc0 < VV)     C[(size_t)(gr0 + 8) * VV + gc0]     = acc[mi][ni][2] + b0;
                if (gc0 + 1 < VV) C[(size_t)(gr0 + 8) * VV + gc0 + 1] = acc[mi][ni][3] + b1;
            }
        }
    }
}

// ---------------------------------------------------------------------------
// K6: in-place log_softmax, float4 + online max/sum
__global__ void k_lsm(float* __restrict__ C) {
    int row = blockIdx.x;
    float4* p4 = (float4*)(C + (size_t)row * VV);   // 1250 float4
    __shared__ float rm[256], rs[256];
    int tid = threadIdx.x;

    float m = -1e30f, s = 0.f;
    for (int i = tid; i < VV / 4; i += 256) {
        float4 v = p4[i];
#pragma unroll
        for (int j = 0; j < 4; j++) {
            float x = (&v.x)[j];
            if (x > m) { s *= __expf(m - x); m = x; }
            s += __expf(x - m);
        }
    }
    rm[tid] = m; rs[tid] = s;
    for (int st = 128; st > 0; st >>= 1) {
        __syncthreads();
        if (tid < st) {
            float m2 = rm[tid + st], s2 = rs[tid + st];
            float M = fmaxf(rm[tid], m2);
            rs[tid] = rs[tid] * __expf(rm[tid] - M) + s2 * __expf(m2 - M);
            rm[tid] = M;
        }
    }
    __syncthreads();
    float lse = rm[0] + logf(rs[0]);

    for (int i = tid; i < VV / 4; i += 256) {
        float4 v = p4[i];
        v.x -= lse; v.y -= lse; v.z -= lse; v.w -= lse;
        p4[i] = v;
    }
}

// ---------------------------------------------------------------------------
extern "C" void kernel_launch(void* const* d_in, const int* in_sizes, int n_in,
                              void* d_out, int out_size) {
    const float* memory = (const float*)d_in[0];
    const int*   ys     = (const int*)d_in[1];
    const float* emb    = (const float*)d_in[3];
    const float* Wih    = (const float*)d_in[4];
    const float* bih    = (const float*)d_in[5];
    const float* Whh    = (const float*)d_in[6];
    const float* bhh    = (const float*)d_in[7];
    const float* Wproj  = (const float*)d_in[8];
    const float* bproj  = (const float*)d_in[9];
    const float* lng    = (const float*)d_in[10];
    const float* lnb    = (const float*)d_in[11];
    const float* Wenc   = (const float*)d_in[12];
    const float* benc   = (const float*)d_in[13];
    const float* Wprd   = (const float*)d_in[14];
    const float* bprd   = (const float*)d_in[15];
    const float* Wout   = (const float*)d_in[16];
    const float* bout   = (const float*)d_in[17];
    float* out = (float*)d_out;

    k_wconv<<<(VV * NI) / 4 / 256, 256>>>(Wout);
    k_whconv<<<(4 * DD * DD) / 4 / 256, 256>>>(Whh);
    dim3 gx(4, Bq * UU);
    k_gx<<<gx, 256>>>(ys, emb, Wih, bih, bhh);
    k_lstm_r<<<Bq, 1024>>>();
    dim3 ge(NI / 256, Bq * TT);
    k_enc<<<ge, 256>>>(memory, Wenc, benc);
    k_proj<<<Bq * UU, 256>>>(Wproj, bproj, lng, lnb, Wprd, bprd);
    k_joint<<<(MM * (NI / 4)) / 256, 256>>>();
    dim3 gg((VV + 127) / 128, (MM + 127) / 128);
    k_gemm_hmma<<<gg, 256>>>(bout, out);
    k_lsm<<<MM, 256>>>(out);
}

// round 6
// speedup vs baseline: 4.9087x; 1.0681x over previous
#include <cuda_runtime.h>
#include <cuda_bf16.h>
#include <cstdint>
#include <math.h>

#define Bq 2
#define TT 200
#define UU 50
#define DD 256
#define NI 2048
#define VV 5000
#define MM (Bq*TT*UU)   /* 20000 */

#define SSTR 40          /* padded smem row stride in bf16 */
#define NST 3            /* gemm pipeline stages */
#define STAGE_ELEMS (128*SSTR)            /* per matrix per stage */
#define GEMM_SMEM (NST*2*STAGE_ELEMS*2)   /* bytes = 61440 */

// Scratch (__device__ globals; no allocations anywhere)
__device__ float g_enc[Bq*TT*NI];
__device__ float g_dec[Bq*UU*NI];
__device__ float g_h[Bq*UU*DD];
__device__ float g_gx[Bq*UU*4*DD];                  // precomputed input gates
__device__ __nv_bfloat16 g_whhb[4*DD*DD];           // W_hh bf16
__device__ __nv_bfloat16 g_jointh[(size_t)MM*NI];   // 82MB bf16
__device__ __nv_bfloat16 g_woutb[(size_t)VV*NI];    // 20MB bf16

__device__ __forceinline__ uint32_t smem_u32(const void* p) {
    uint32_t a;
    asm("{ .reg .u64 t; cvta.to.shared.u64 t, %1; cvt.u32.u64 %0, t; }" : "=r"(a) : "l"(p));
    return a;
}

__device__ __forceinline__ float tanh_fast(float x) {
    float r;
    asm("tanh.approx.f32 %0, %1;" : "=f"(r) : "f"(x));
    return r;
}

// ---------------------------------------------------------------------------
// K1: enc = memory @ W_enc^T + b_enc
__global__ void k_enc(const float* __restrict__ mem,
                      const float* __restrict__ W,
                      const float* __restrict__ bias) {
    __shared__ float sx[DD];
    int row = blockIdx.y;
    int j = blockIdx.x * 256 + threadIdx.x;
    sx[threadIdx.x] = mem[row * DD + threadIdx.x];
    __syncthreads();
    const float4* w4 = reinterpret_cast<const float4*>(W + (size_t)j * DD);
    const float4* x4 = reinterpret_cast<const float4*>(sx);
    float acc = bias[j];
#pragma unroll 16
    for (int k = 0; k < DD / 4; k++) {
        float4 w = w4[k], x = x4[k];
        acc += w.x * x.x + w.y * x.y + w.z * x.z + w.w * x.w;
    }
    g_enc[(size_t)row * NI + j] = acc;
}

// ---------------------------------------------------------------------------
// K2a: gx[row, j] = emb[tok[row]] . W_ih[j] + b_ih[j] + b_hh[j]
__global__ void k_gx(const int* __restrict__ tok,
                     const float* __restrict__ emb,
                     const float* __restrict__ Wih, const float* __restrict__ bih,
                     const float* __restrict__ bhh) {
    __shared__ float sx[DD];
    int row = blockIdx.y;                  // b*UU + u
    int j = blockIdx.x * 256 + threadIdx.x;
    if (threadIdx.x < DD) {
        int t = tok[row];
        sx[threadIdx.x] = emb[(size_t)t * DD + threadIdx.x];
    }
    __syncthreads();
    const float4* w4 = (const float4*)(Wih + (size_t)j * DD);
    const float4* x4 = (const float4*)sx;
    float acc = bih[j] + bhh[j];
#pragma unroll 16
    for (int k = 0; k < DD / 4; k++) {
        float4 w = w4[k], x = x4[k];
        acc += w.x * x.x + w.y * x.y + w.z * x.z + w.w * x.w;
    }
    g_gx[(size_t)row * (4 * DD) + j] = acc;
}

// K2b: W_hh -> bf16
__global__ void k_whconv(const float* __restrict__ W) {
    size_t i = ((size_t)blockIdx.x * 256 + threadIdx.x) * 4;
    float4 v = *(const float4*)(W + i);
    __nv_bfloat162 lo = __floats2bfloat162_rn(v.x, v.y);
    __nv_bfloat162 hi = __floats2bfloat162_rn(v.z, v.w);
    uint2 pk;
    pk.x = *(uint32_t*)&lo;
    pk.y = *(uint32_t*)&hi;
    *(uint2*)&g_whhb[i] = pk;
}

// K2c: recurrent LSTM, bf16 W_hh, 4 independent accumulator chains
__device__ __forceinline__ void dot8(float& acc, uint4 q, float4 ha, float4 hb) {
    float2 c0 = __bfloat1622float2(*(const __nv_bfloat162*)&q.x);
    float2 c1 = __bfloat1622float2(*(const __nv_bfloat162*)&q.y);
    float2 c2 = __bfloat1622float2(*(const __nv_bfloat162*)&q.z);
    float2 c3 = __bfloat1622float2(*(const __nv_bfloat162*)&q.w);
    acc += c0.x * ha.x + c0.y * ha.y + c1.x * ha.z + c1.y * ha.w
         + c2.x * hb.x + c2.y * hb.y + c3.x * hb.z + c3.y * hb.w;
}

__global__ void k_lstm_r() {
    int b = blockIdx.x;
    int tid = threadIdx.x;
    __shared__ float sh[DD], sc[DD], sg[4 * DD];
    if (tid < DD) { sh[tid] = 0.f; sc[tid] = 0.f; }
    const uint4* w = (const uint4*)(g_whhb + (size_t)tid * DD);   // 32 x uint4
    const float4* sh4 = (const float4*)sh;
    __syncthreads();
    for (int u = 0; u < UU; u++) {
        float gx = g_gx[(size_t)(b * UU + u) * (4 * DD) + tid];
        float a0 = 0.f, a1 = 0.f, a2 = 0.f, a3 = 0.f;
#pragma unroll
        for (int k = 0; k < 32; k += 4) {
            uint4 q0 = w[k], q1 = w[k + 1], q2 = w[k + 2], q3 = w[k + 3];
            float4 h0 = sh4[2 * k],     h1 = sh4[2 * k + 1];
            float4 h2 = sh4[2 * k + 2], h3 = sh4[2 * k + 3];
            float4 h4 = sh4[2 * k + 4], h5 = sh4[2 * k + 5];
            float4 h6 = sh4[2 * k + 6], h7 = sh4[2 * k + 7];
            dot8(a0, q0, h0, h1);
            dot8(a1, q1, h2, h3);
            dot8(a2, q2, h4, h5);
            dot8(a3, q3, h6, h7);
        }
        sg[tid] = gx + ((a0 + a1) + (a2 + a3));
        __syncthreads();
        if (tid < DD) {
            float ig = 1.f / (1.f + expf(-sg[tid]));
            float fg = 1.f / (1.f + expf(-sg[DD + tid]));
            float gg = tanhf(sg[2 * DD + tid]);
            float og = 1.f / (1.f + expf(-sg[3 * DD + tid]));
            float c = fg * sc[tid] + ig * gg;
            float h = og * tanhf(c);
            sc[tid] = c;
            sh[tid] = h;
            g_h[(b * UU + u) * DD + tid] = h;
        }
        __syncthreads();
    }
}

// ---------------------------------------------------------------------------
// K3: proj + LayerNorm + dec pre-linear
__global__ void k_proj(const float* __restrict__ Wp, const float* __restrict__ bp,
                       const float* __restrict__ lng, const float* __restrict__ lnb,
                       const float* __restrict__ Wprd, const float* __restrict__ bprd) {
    int row = blockIdx.x;
    int tid = threadIdx.x;
    __shared__ float shh[DD], sy[DD], red[256];
    shh[tid] = g_h[row * DD + tid];
    __syncthreads();
    {
        const float4* h4 = (const float4*)shh;
        const float4* w4 = (const float4*)(Wp + (size_t)tid * DD);
        float p = bp[tid];
#pragma unroll 16
        for (int k = 0; k < DD / 4; k++) {
            float4 w = w4[k], h = h4[k];
            p += w.x * h.x + w.y * h.y + w.z * h.z + w.w * h.w;
        }
        red[tid] = p;
        for (int s = 128; s > 0; s >>= 1) { __syncthreads(); if (tid < s) red[tid] += red[tid + s]; }
        __syncthreads();
        float mu = red[0] * (1.f / DD);
        __syncthreads();
        float d = p - mu;
        red[tid] = d * d;
        for (int s = 128; s > 0; s >>= 1) { __syncthreads(); if (tid < s) red[tid] += red[tid + s]; }
        __syncthreads();
        float var = red[0] * (1.f / DD);
        float y = d * rsqrtf(var + 1e-5f) * lng[tid] + lnb[tid];
        sy[tid] = y;
    }
    __syncthreads();
    const float4* y4 = (const float4*)sy;
    for (int j = tid; j < NI; j += 256) {
        const float4* w4 = (const float4*)(Wprd + (size_t)j * DD);
        float acc = bprd[j];
#pragma unroll 16
        for (int k = 0; k < DD / 4; k++) {
            float4 w = w4[k], y = y4[k];
            acc += w.x * y.x + w.y * y.y + w.z * y.z + w.w * y.w;
        }
        g_dec[row * NI + j] = acc;
    }
}

// ---------------------------------------------------------------------------
// K4: joint = tanh(enc + dec) -> bf16 (MUFU tanh)
__global__ void k_joint() {
    int idx = blockIdx.x * 256 + threadIdx.x;       // float4 index
    int r = idx / (NI / 4);
    int k = (idx % (NI / 4)) * 4;
    int b = r / (TT * UU);
    int rem = r % (TT * UU);
    int t = rem / UU;
    int u = rem % UU;
    float4 e = *(const float4*)&g_enc[(size_t)(b * TT + t) * NI + k];
    float4 d = *(const float4*)&g_dec[(size_t)(b * UU + u) * NI + k];
    __nv_bfloat162 lo = __floats2bfloat162_rn(tanh_fast(e.x + d.x), tanh_fast(e.y + d.y));
    __nv_bfloat162 hi = __floats2bfloat162_rn(tanh_fast(e.z + d.z), tanh_fast(e.w + d.w));
    uint2 pk;
    pk.x = *(uint32_t*)&lo;
    pk.y = *(uint32_t*)&hi;
    *(uint2*)&g_jointh[(size_t)r * NI + k] = pk;
}

// ---------------------------------------------------------------------------
// K4b: W_out -> bf16
__global__ void k_wconv(const float* __restrict__ W) {
    size_t i = ((size_t)blockIdx.x * 256 + threadIdx.x) * 4;
    float4 v = *(const float4*)(W + i);
    __nv_bfloat162 lo = __floats2bfloat162_rn(v.x, v.y);
    __nv_bfloat162 hi = __floats2bfloat162_rn(v.z, v.w);
    uint2 pk;
    pk.x = *(uint32_t*)&lo;
    pk.y = *(uint32_t*)&hi;
    *(uint2*)&g_woutb[i] = pk;
}

// ---------------------------------------------------------------------------
// K5: logits = joint @ W_out^T + b_out via mma.sync bf16 + ldmatrix
// 128x128x32 CTA tile, 8 warps (2x4), warp = 64x32, 3-stage cp.async pipeline
#define NIT (NI/32)   /* 64 */

__device__ __forceinline__ void cp16(uint32_t dst, const void* src, int sz) {
    asm volatile("cp.async.cg.shared.global [%0], [%1], 16, %2;"
                 :: "r"(dst), "l"(src), "r"(sz));
}

#define LDM_X4(r0, r1, r2, r3, a) \
    asm volatile("ldmatrix.sync.aligned.m8n8.x4.shared.b16 {%0,%1,%2,%3}, [%4];" \
                 : "=r"(r0), "=r"(r1), "=r"(r2), "=r"(r3) : "r"(a))

extern __shared__ __nv_bfloat16 dsm[];   // NST stages: [A(128*SSTR) | B(128*SSTR)]

__global__ void __launch_bounds__(256, 2) k_gemm_hmma(const float* __restrict__ bias,
                                                      float* __restrict__ C) {
    const int tid = threadIdx.x;
    const int wid = tid >> 5, lid = tid & 31;
    const int wm = wid >> 2, wn = wid & 3;       // warp grid 2x4
    const int g = lid >> 2, t = lid & 3;         // mma lane decomposition
    const int bm = blockIdx.y, bn = blockIdx.x;

    // ldmatrix per-lane tile offsets (elements)
    const int lq = lid >> 3, lr_ = lid & 7;
    const int ld_row = ((lq & 1) << 3) + lr_;    // 0..15
    const int ld_col = (lq >> 1) << 3;           // 0 or 8
    int aoff[4], boff[2];
#pragma unroll
    for (int mi = 0; mi < 4; mi++)
        aoff[mi] = (wm * 64 + mi * 16 + ld_row) * SSTR + ld_col;
#pragma unroll
    for (int p = 0; p < 2; p++)
        boff[p] = (wn * 32 + p * 16 + ld_row) * SSTR + ld_col;

    uint32_t sbase[NST];
#pragma unroll
    for (int s = 0; s < NST; s++) sbase[s] = smem_u32(dsm + s * 2 * STAGE_ELEMS);

    const int row0 = tid >> 2;          // 0..63  (two rows: row0, row0+64)
    const int ch = tid & 3;             // 16B chunk within 64B row

    // per-thread global srcs (row-clamped, predicated by size)
    const int rA0 = bm * 128 + row0, rA1 = rA0 + 64;
    const int rB0 = bn * 128 + row0, rB1 = rB0 + 64;
    const __nv_bfloat16* srcA0 = g_jointh + (size_t)(rA0 < MM ? rA0 : MM - 1) * NI + ch * 8;
    const __nv_bfloat16* srcA1 = g_jointh + (size_t)(rA1 < MM ? rA1 : MM - 1) * NI + ch * 8;
    const __nv_bfloat16* srcB0 = g_woutb + (size_t)(rB0 < VV ? rB0 : VV - 1) * NI + ch * 8;
    const __nv_bfloat16* srcB1 = g_woutb + (size_t)(rB1 < VV ? rB1 : VV - 1) * NI + ch * 8;
    const int szA0 = rA0 < MM ? 16 : 0, szA1 = rA1 < MM ? 16 : 0;
    const int szB0 = rB0 < VV ? 16 : 0, szB1 = rB1 < VV ? 16 : 0;
    const uint32_t dA0 = (row0 * SSTR + ch * 8) * 2;
    const uint32_t dA1 = ((row0 + 64) * SSTR + ch * 8) * 2;
    const uint32_t dB0 = dA0 + STAGE_ELEMS * 2;
    const uint32_t dB1 = dA1 + STAGE_ELEMS * 2;

#define LOAD_STAGE(s, it) do { \
    int ck = (it) * 32; \
    uint32_t sb = sbase[s]; \
    cp16(sb + dA0, srcA0 + ck, szA0); \
    cp16(sb + dA1, srcA1 + ck, szA1); \
    cp16(sb + dB0, srcB0 + ck, szB0); \
    cp16(sb + dB1, srcB1 + ck, szB1); \
} while (0)

    float acc[4][4][4];
#pragma unroll
    for (int i = 0; i < 4; i++)
#pragma unroll
        for (int j = 0; j < 4; j++)
#pragma unroll
            for (int k = 0; k < 4; k++) acc[i][j][k] = 0.f;

    // prologue
    LOAD_STAGE(0, 0);
    asm volatile("cp.async.commit_group;");
    LOAD_STAGE(1, 1);
    asm volatile("cp.async.commit_group;");

    int st = 0;
    for (int it = 0; it < NIT; it++) {
        asm volatile("cp.async.wait_group 1;");
        __syncthreads();
        if (it + 2 < NIT) {
            int s2 = st + 2; if (s2 >= NST) s2 -= NST;
            LOAD_STAGE(s2, it + 2);
        }
        asm volatile("cp.async.commit_group;");

        const uint32_t asb = sbase[st];
        const uint32_t bsb = asb + STAGE_ELEMS * 2;
#pragma unroll
        for (int ks = 0; ks < 2; ks++) {
            const int kk = ks * 16;
            uint32_t ar[4][4], br[2][4];
#pragma unroll
            for (int mi = 0; mi < 4; mi++)
                LDM_X4(ar[mi][0], ar[mi][1], ar[mi][2], ar[mi][3],
                       asb + ((aoff[mi] + kk) << 1));
#pragma unroll
            for (int p = 0; p < 2; p++)
                LDM_X4(br[p][0], br[p][1], br[p][2], br[p][3],
                       bsb + ((boff[p] + kk) << 1));
#pragma unroll
            for (int mi = 0; mi < 4; mi++) {
#pragma unroll
                for (int p = 0; p < 2; p++) {
                    asm volatile(
                        "mma.sync.aligned.m16n8k16.row.col.f32.bf16.bf16.f32 "
                        "{%0,%1,%2,%3}, {%4,%5,%6,%7}, {%8,%9}, {%0,%1,%2,%3};"
                        : "+f"(acc[mi][2 * p][0]), "+f"(acc[mi][2 * p][1]),
                          "+f"(acc[mi][2 * p][2]), "+f"(acc[mi][2 * p][3])
                        : "r"(ar[mi][0]), "r"(ar[mi][1]), "r"(ar[mi][2]), "r"(ar[mi][3]),
                          "r"(br[p][0]), "r"(br[p][2]));
                    asm volatile(
                        "mma.sync.aligned.m16n8k16.row.col.f32.bf16.bf16.f32 "
                        "{%0,%1,%2,%3}, {%4,%5,%6,%7}, {%8,%9}, {%0,%1,%2,%3};"
                        : "+f"(acc[mi][2 * p + 1][0]), "+f"(acc[mi][2 * p + 1][1]),
                          "+f"(acc[mi][2 * p + 1][2]), "+f"(acc[mi][2 * p + 1][3])
                        : "r"(ar[mi][0]), "r"(ar[mi][1]), "r"(ar[mi][2]), "r"(ar[mi][3]),
                          "r"(br[p][1]), "r"(br[p][3]));
                }
            }
        }
        st++; if (st >= NST) st = 0;
    }

    // epilogue: bias add + guarded store
#pragma unroll
    for (int mi = 0; mi < 4; mi++) {
        int gr0 = bm * 128 + wm * 64 + mi * 16 + g;
#pragma unroll
        for (int ni = 0; ni < 4; ni++) {
            int gc0 = bn * 128 + wn * 32 + ni * 8 + 2 * t;
            float b0 = (gc0 < VV) ? __ldg(&bias[gc0]) : 0.f;
            float b1 = (gc0 + 1 < VV) ? __ldg(&bias[gc0 + 1]) : 0.f;
            if (gr0 < MM) {
                if (gc0 < VV)     C[(size_t)gr0 * VV + gc0]     = acc[mi][ni][0] + b0;
                if (gc0 + 1 < VV) C[(size_t)gr0 * VV + gc0 + 1] = acc[mi][ni][1] + b1;
            }
            if (gr0 + 8 < MM) {
                if (gc0 < VV)     C[(size_t)(gr0 + 8) * VV + gc0]     = acc[mi][ni][2] + b0;
                if (gc0 + 1 < VV) C[(size_t)(gr0 + 8) * VV + gc0 + 1] = acc[mi][ni][3] + b1;
            }
        }
    }
}

// ---------------------------------------------------------------------------
// K6: in-place log_softmax, float4 + online max/sum
__global__ void k_lsm(float* __restrict__ C) {
    int row = blockIdx.x;
    float4* p4 = (float4*)(C + (size_t)row * VV);   // 1250 float4
    __shared__ float rm[256], rs[256];
    int tid = threadIdx.x;

    float m = -1e30f, s = 0.f;
    for (int i = tid; i < VV / 4; i += 256) {
        float4 v = p4[i];
#pragma unroll
        for (int j = 0; j < 4; j++) {
            float x = (&v.x)[j];
            if (x > m) { s *= __expf(m - x); m = x; }
            s += __expf(x - m);
        }
    }
    rm[tid] = m; rs[tid] = s;
    for (int st = 128; st > 0; st >>= 1) {
        __syncthreads();
        if (tid < st) {
            float m2 = rm[tid + st], s2 = rs[tid + st];
            float M = fmaxf(rm[tid], m2);
            rs[tid] = rs[tid] * __expf(rm[tid] - M) + s2 * __expf(m2 - M);
            rm[tid] = M;
        }
    }
    __syncthreads();
    float lse = rm[0] + logf(rs[0]);

    for (int i = tid; i < VV / 4; i += 256) {
        float4 v = p4[i];
        v.x -= lse; v.y -= lse; v.z -= lse; v.w -= lse;
        p4[i] = v;
    }
}

// ---------------------------------------------------------------------------
extern "C" void kernel_launch(void* const* d_in, const int* in_sizes, int n_in,
                              void* d_out, int out_size) {
    const float* memory = (const float*)d_in[0];
    const int*   ys     = (const int*)d_in[1];
    const float* emb    = (const float*)d_in[3];
    const float* Wih    = (const float*)d_in[4];
    const float* bih    = (const float*)d_in[5];
    const float* Whh    = (const float*)d_in[6];
    const float* bhh    = (const float*)d_in[7];
    const float* Wproj  = (const float*)d_in[8];
    const float* bproj  = (const float*)d_in[9];
    const float* lng    = (const float*)d_in[10];
    const float* lnb    = (const float*)d_in[11];
    const float* Wenc   = (const float*)d_in[12];
    const float* benc   = (const float*)d_in[13];
    const float* Wprd   = (const float*)d_in[14];
    const float* bprd   = (const float*)d_in[15];
    const float* Wout   = (const float*)d_in[16];
    const float* bout   = (const float*)d_in[17];
    float* out = (float*)d_out;

    cudaFuncSetAttribute(k_gemm_hmma, cudaFuncAttributeMaxDynamicSharedMemorySize, GEMM_SMEM);

    k_wconv<<<(VV * NI) / 4 / 256, 256>>>(Wout);
    k_whconv<<<(4 * DD * DD) / 4 / 256, 256>>>(Whh);
    dim3 gx(4, Bq * UU);
    k_gx<<<gx, 256>>>(ys, emb, Wih, bih, bhh);
    k_lstm_r<<<Bq, 1024>>>();
    dim3 ge(NI / 256, Bq * TT);
    k_enc<<<ge, 256>>>(memory, Wenc, benc);
    k_proj<<<Bq * UU, 256>>>(Wproj, bproj, lng, lnb, Wprd, bprd);
    k_joint<<<(MM * (NI / 4)) / 256, 256>>>();
    dim3 gg((VV + 127) / 128, (MM + 127) / 128);
    k_gemm_hmma<<<gg, 256, GEMM_SMEM>>>(bout, out);
    k_lsm<<<MM, 256>>>(out);
}

// round 7
// speedup vs baseline: 5.7716x; 1.1758x over previous
#include <cuda_runtime.h>
#include <cuda_bf16.h>
#include <cstdint>
#include <math.h>

#define Bq 2
#define TT 200
#define UU 50
#define DD 256
#define NI 2048
#define VV 5000
#define MM (Bq*TT*UU)   /* 20000 */

#define SSTR 40          /* padded smem row stride in bf16 */
#define NST 3            /* gemm pipeline stages */
#define STAGE_ELEMS (128*SSTR)            /* per matrix per stage */
#define GEMM_SMEM (NST*2*STAGE_ELEMS*2)   /* bytes = 61440 */

// Scratch (__device__ globals; no allocations anywhere)
__device__ float g_enc[Bq*TT*NI];
__device__ float g_dec[Bq*UU*NI];
__device__ float g_h[Bq*UU*DD];
__device__ float g_gx[Bq*UU*4*DD];                  // precomputed input gates
__device__ __nv_bfloat16 g_whhT[DD*4*DD];           // W_hh^T (k-major) bf16
__device__ __nv_bfloat16 g_jointh[(size_t)MM*NI];   // 82MB bf16
__device__ __nv_bfloat16 g_woutb[(size_t)VV*NI];    // 20MB bf16

__device__ __forceinline__ uint32_t smem_u32(const void* p) {
    uint32_t a;
    asm("{ .reg .u64 t; cvta.to.shared.u64 t, %1; cvt.u32.u64 %0, t; }" : "=r"(a) : "l"(p));
    return a;
}

__device__ __forceinline__ float tanh_fast(float x) {
    float r;
    asm("tanh.approx.f32 %0, %1;" : "=f"(r) : "f"(x));
    return r;
}

// ---------------------------------------------------------------------------
// K1: enc = memory @ W_enc^T + b_enc
__global__ void k_enc(const float* __restrict__ mem,
                      const float* __restrict__ W,
                      const float* __restrict__ bias) {
    __shared__ float sx[DD];
    int row = blockIdx.y;
    int j = blockIdx.x * 256 + threadIdx.x;
    sx[threadIdx.x] = mem[row * DD + threadIdx.x];
    __syncthreads();
    const float4* w4 = reinterpret_cast<const float4*>(W + (size_t)j * DD);
    const float4* x4 = reinterpret_cast<const float4*>(sx);
    float acc = bias[j];
#pragma unroll 16
    for (int k = 0; k < DD / 4; k++) {
        float4 w = w4[k], x = x4[k];
        acc += w.x * x.x + w.y * x.y + w.z * x.z + w.w * x.w;
    }
    g_enc[(size_t)row * NI + j] = acc;
}

// ---------------------------------------------------------------------------
// K2a: gx[row, j] = emb[tok[row]] . W_ih[j] + b_ih[j] + b_hh[j]
__global__ void k_gx(const int* __restrict__ tok,
                     const float* __restrict__ emb,
                     const float* __restrict__ Wih, const float* __restrict__ bih,
                     const float* __restrict__ bhh) {
    __shared__ float sx[DD];
    int row = blockIdx.y;                  // b*UU + u
    int j = blockIdx.x * 256 + threadIdx.x;
    if (threadIdx.x < DD) {
        int t = tok[row];
        sx[threadIdx.x] = emb[(size_t)t * DD + threadIdx.x];
    }
    __syncthreads();
    const float4* w4 = (const float4*)(Wih + (size_t)j * DD);
    const float4* x4 = (const float4*)sx;
    float acc = bih[j] + bhh[j];
#pragma unroll 16
    for (int k = 0; k < DD / 4; k++) {
        float4 w = w4[k], x = x4[k];
        acc += w.x * x.x + w.y * x.y + w.z * x.z + w.w * x.w;
    }
    g_gx[(size_t)row * (4 * DD) + j] = acc;
}

// K2b: W_hh -> bf16, transposed to k-major: g_whhT[k*1024 + j] = W[j*256 + k]
__global__ void k_whconvT(const float* __restrict__ W) {
    int idx = blockIdx.x * 256 + threadIdx.x;   // 0 .. 4*DD*DD-1, coalesced read
    int j = idx >> 8;           // 0..1023
    int k = idx & 255;          // 0..255
    g_whhT[k * (4 * DD) + j] = __float2bfloat16(W[idx]);
}

// K2c: recurrent LSTM, coalesced k-major weights, K-split 8 + smem reduction
__global__ void __launch_bounds__(1024) k_lstm_r2() {
    int b = blockIdx.x;
    int tid = threadIdx.x;
    __shared__ float sh[DD], sc[DD], sg[4 * DD];
    __shared__ float sp[8 * 4 * DD];            // 8 k-slices x 1024 partials
    const int ks = tid >> 7;                    // 0..7  -> k slice [32*ks, 32*ks+32)
    const int j0 = (tid & 127) * 8;             // 8 adjacent gate outputs
    const int k0 = ks * 32;
    if (tid < DD) { sh[tid] = 0.f; sc[tid] = 0.f; }
    __syncthreads();

    const __nv_bfloat16* wp = g_whhT + (size_t)k0 * (4 * DD) + j0;

    for (int u = 0; u < UU; u++) {
        float acc[8];
#pragma unroll
        for (int i = 0; i < 8; i++) acc[i] = 0.f;

#pragma unroll
        for (int half = 0; half < 2; half++) {
            float hreg[16];
#pragma unroll
            for (int i = 0; i < 4; i++)
                *(float4*)&hreg[4 * i] = *(const float4*)&sh[k0 + half * 16 + 4 * i];
#pragma unroll
            for (int k = 0; k < 16; k++) {
                uint4 q = *(const uint4*)(wp + (size_t)(half * 16 + k) * (4 * DD));
                float2 c0 = __bfloat1622float2(*(const __nv_bfloat162*)&q.x);
                float2 c1 = __bfloat1622float2(*(const __nv_bfloat162*)&q.y);
                float2 c2 = __bfloat1622float2(*(const __nv_bfloat162*)&q.z);
                float2 c3 = __bfloat1622float2(*(const __nv_bfloat162*)&q.w);
                float hk = hreg[k];
                acc[0] += hk * c0.x; acc[1] += hk * c0.y;
                acc[2] += hk * c1.x; acc[3] += hk * c1.y;
                acc[4] += hk * c2.x; acc[5] += hk * c2.y;
                acc[6] += hk * c3.x; acc[7] += hk * c3.y;
            }
        }
        *(float4*)&sp[ks * 1024 + j0]     = make_float4(acc[0], acc[1], acc[2], acc[3]);
        *(float4*)&sp[ks * 1024 + j0 + 4] = make_float4(acc[4], acc[5], acc[6], acc[7]);
        __syncthreads();
        {
            float gacc = g_gx[(size_t)(b * UU + u) * (4 * DD) + tid];
#pragma unroll
            for (int s = 0; s < 8; s++) gacc += sp[s * 1024 + tid];
            sg[tid] = gacc;
        }
        __syncthreads();
        if (tid < DD) {
            float ig = 1.f / (1.f + expf(-sg[tid]));
            float fg = 1.f / (1.f + expf(-sg[DD + tid]));
            float gg = tanhf(sg[2 * DD + tid]);
            float og = 1.f / (1.f + expf(-sg[3 * DD + tid]));
            float c = fg * sc[tid] + ig * gg;
            float h = og * tanhf(c);
            sc[tid] = c;
            sh[tid] = h;
            g_h[(b * UU + u) * DD + tid] = h;
        }
        __syncthreads();
    }
}

// ---------------------------------------------------------------------------
// K3: proj + LayerNorm + dec pre-linear
__global__ void k_proj(const float* __restrict__ Wp, const float* __restrict__ bp,
                       const float* __restrict__ lng, const float* __restrict__ lnb,
                       const float* __restrict__ Wprd, const float* __restrict__ bprd) {
    int row = blockIdx.x;
    int tid = threadIdx.x;
    __shared__ float shh[DD], sy[DD], red[256];
    shh[tid] = g_h[row * DD + tid];
    __syncthreads();
    {
        const float4* h4 = (const float4*)shh;
        const float4* w4 = (const float4*)(Wp + (size_t)tid * DD);
        float p = bp[tid];
#pragma unroll 16
        for (int k = 0; k < DD / 4; k++) {
            float4 w = w4[k], h = h4[k];
            p += w.x * h.x + w.y * h.y + w.z * h.z + w.w * h.w;
        }
        red[tid] = p;
        for (int s = 128; s > 0; s >>= 1) { __syncthreads(); if (tid < s) red[tid] += red[tid + s]; }
        __syncthreads();
        float mu = red[0] * (1.f / DD);
        __syncthreads();
        float d = p - mu;
        red[tid] = d * d;
        for (int s = 128; s > 0; s >>= 1) { __syncthreads(); if (tid < s) red[tid] += red[tid + s]; }
        __syncthreads();
        float var = red[0] * (1.f / DD);
        float y = d * rsqrtf(var + 1e-5f) * lng[tid] + lnb[tid];
        sy[tid] = y;
    }
    __syncthreads();
    const float4* y4 = (const float4*)sy;
    for (int j = tid; j < NI; j += 256) {
        const float4* w4 = (const float4*)(Wprd + (size_t)j * DD);
        float acc = bprd[j];
#pragma unroll 16
        for (int k = 0; k < DD / 4; k++) {
            float4 w = w4[k], y = y4[k];
            acc += w.x * y.x + w.y * y.y + w.z * y.z + w.w * y.w;
        }
        g_dec[row * NI + j] = acc;
    }
}

// ---------------------------------------------------------------------------
// K4: joint = tanh(enc + dec) -> bf16 (MUFU tanh)
__global__ void k_joint() {
    int idx = blockIdx.x * 256 + threadIdx.x;       // float4 index
    int r = idx / (NI / 4);
    int k = (idx % (NI / 4)) * 4;
    int b = r / (TT * UU);
    int rem = r % (TT * UU);
    int t = rem / UU;
    int u = rem % UU;
    float4 e = *(const float4*)&g_enc[(size_t)(b * TT + t) * NI + k];
    float4 d = *(const float4*)&g_dec[(size_t)(b * UU + u) * NI + k];
    __nv_bfloat162 lo = __floats2bfloat162_rn(tanh_fast(e.x + d.x), tanh_fast(e.y + d.y));
    __nv_bfloat162 hi = __floats2bfloat162_rn(tanh_fast(e.z + d.z), tanh_fast(e.w + d.w));
    uint2 pk;
    pk.x = *(uint32_t*)&lo;
    pk.y = *(uint32_t*)&hi;
    *(uint2*)&g_jointh[(size_t)r * NI + k] = pk;
}

// ---------------------------------------------------------------------------
// K4b: W_out -> bf16
__global__ void k_wconv(const float* __restrict__ W) {
    size_t i = ((size_t)blockIdx.x * 256 + threadIdx.x) * 4;
    float4 v = *(const float4*)(W + i);
    __nv_bfloat162 lo = __floats2bfloat162_rn(v.x, v.y);
    __nv_bfloat162 hi = __floats2bfloat162_rn(v.z, v.w);
    uint2 pk;
    pk.x = *(uint32_t*)&lo;
    pk.y = *(uint32_t*)&hi;
    *(uint2*)&g_woutb[i] = pk;
}

// ---------------------------------------------------------------------------
// K5: logits = joint @ W_out^T + b_out via mma.sync bf16 + ldmatrix
// 128x128x32 CTA tile, 8 warps (2x4), warp = 64x32, 3-stage cp.async pipeline
#define NIT (NI/32)   /* 64 */

__device__ __forceinline__ void cp16(uint32_t dst, const void* src, int sz) {
    asm volatile("cp.async.cg.shared.global [%0], [%1], 16, %2;"
                 :: "r"(dst), "l"(src), "r"(sz));
}

#define LDM_X4(r0, r1, r2, r3, a) \
    asm volatile("ldmatrix.sync.aligned.m8n8.x4.shared.b16 {%0,%1,%2,%3}, [%4];" \
                 : "=r"(r0), "=r"(r1), "=r"(r2), "=r"(r3) : "r"(a))

extern __shared__ __nv_bfloat16 dsm[];   // NST stages: [A(128*SSTR) | B(128*SSTR)]

__global__ void __launch_bounds__(256, 2) k_gemm_hmma(const float* __restrict__ bias,
                                                      float* __restrict__ C) {
    const int tid = threadIdx.x;
    const int wid = tid >> 5, lid = tid & 31;
    const int wm = wid >> 2, wn = wid & 3;       // warp grid 2x4
    const int g = lid >> 2, t = lid & 3;         // mma lane decomposition
    const int bm = blockIdx.y, bn = blockIdx.x;

    // ldmatrix per-lane tile offsets (elements)
    const int lq = lid >> 3, lr_ = lid & 7;
    const int ld_row = ((lq & 1) << 3) + lr_;    // 0..15
    const int ld_col = (lq >> 1) << 3;           // 0 or 8
    int aoff[4], boff[2];
#pragma unroll
    for (int mi = 0; mi < 4; mi++)
        aoff[mi] = (wm * 64 + mi * 16 + ld_row) * SSTR + ld_col;
#pragma unroll
    for (int p = 0; p < 2; p++)
        boff[p] = (wn * 32 + p * 16 + ld_row) * SSTR + ld_col;

    uint32_t sbase[NST];
#pragma unroll
    for (int s = 0; s < NST; s++) sbase[s] = smem_u32(dsm + s * 2 * STAGE_ELEMS);

    const int row0 = tid >> 2;          // 0..63  (two rows: row0, row0+64)
    const int ch = tid & 3;             // 16B chunk within 64B row

    // per-thread global srcs (row-clamped, predicated by size)
    const int rA0 = bm * 128 + row0, rA1 = rA0 + 64;
    const int rB0 = bn * 128 + row0, rB1 = rB0 + 64;
    const __nv_bfloat16* srcA0 = g_jointh + (size_t)(rA0 < MM ? rA0 : MM - 1) * NI + ch * 8;
    const __nv_bfloat16* srcA1 = g_jointh + (size_t)(rA1 < MM ? rA1 : MM - 1) * NI + ch * 8;
    const __nv_bfloat16* srcB0 = g_woutb + (size_t)(rB0 < VV ? rB0 : VV - 1) * NI + ch * 8;
    const __nv_bfloat16* srcB1 = g_woutb + (size_t)(rB1 < VV ? rB1 : VV - 1) * NI + ch * 8;
    const int szA0 = rA0 < MM ? 16 : 0, szA1 = rA1 < MM ? 16 : 0;
    const int szB0 = rB0 < VV ? 16 : 0, szB1 = rB1 < VV ? 16 : 0;
    const uint32_t dA0 = (row0 * SSTR + ch * 8) * 2;
    const uint32_t dA1 = ((row0 + 64) * SSTR + ch * 8) * 2;
    const uint32_t dB0 = dA0 + STAGE_ELEMS * 2;
    const uint32_t dB1 = dA1 + STAGE_ELEMS * 2;

#define LOAD_STAGE(s, it) do { \
    int ck = (it) * 32; \
    uint32_t sb = sbase[s]; \
    cp16(sb + dA0, srcA0 + ck, szA0); \
    cp16(sb + dA1, srcA1 + ck, szA1); \
    cp16(sb + dB0, srcB0 + ck, szB0); \
    cp16(sb + dB1, srcB1 + ck, szB1); \
} while (0)

    float acc[4][4][4];
#pragma unroll
    for (int i = 0; i < 4; i++)
#pragma unroll
        for (int j = 0; j < 4; j++)
#pragma unroll
            for (int k = 0; k < 4; k++) acc[i][j][k] = 0.f;

    // prologue
    LOAD_STAGE(0, 0);
    asm volatile("cp.async.commit_group;");
    LOAD_STAGE(1, 1);
    asm volatile("cp.async.commit_group;");

    int st = 0;
    for (int it = 0; it < NIT; it++) {
        asm volatile("cp.async.wait_group 1;");
        __syncthreads();
        if (it + 2 < NIT) {
            int s2 = st + 2; if (s2 >= NST) s2 -= NST;
            LOAD_STAGE(s2, it + 2);
        }
        asm volatile("cp.async.commit_group;");

        const uint32_t asb = sbase[st];
        const uint32_t bsb = asb + STAGE_ELEMS * 2;
#pragma unroll
        for (int ks = 0; ks < 2; ks++) {
            const int kk = ks * 16;
            uint32_t ar[4][4], br[2][4];
#pragma unroll
            for (int mi = 0; mi < 4; mi++)
                LDM_X4(ar[mi][0], ar[mi][1], ar[mi][2], ar[mi][3],
                       asb + ((aoff[mi] + kk) << 1));
#pragma unroll
            for (int p = 0; p < 2; p++)
                LDM_X4(br[p][0], br[p][1], br[p][2], br[p][3],
                       bsb + ((boff[p] + kk) << 1));
#pragma unroll
            for (int mi = 0; mi < 4; mi++) {
#pragma unroll
                for (int p = 0; p < 2; p++) {
                    asm volatile(
                        "mma.sync.aligned.m16n8k16.row.col.f32.bf16.bf16.f32 "
                        "{%0,%1,%2,%3}, {%4,%5,%6,%7}, {%8,%9}, {%0,%1,%2,%3};"
                        : "+f"(acc[mi][2 * p][0]), "+f"(acc[mi][2 * p][1]),
                          "+f"(acc[mi][2 * p][2]), "+f"(acc[mi][2 * p][3])
                        : "r"(ar[mi][0]), "r"(ar[mi][1]), "r"(ar[mi][2]), "r"(ar[mi][3]),
                          "r"(br[p][0]), "r"(br[p][2]));
                    asm volatile(
                        "mma.sync.aligned.m16n8k16.row.col.f32.bf16.bf16.f32 "
                        "{%0,%1,%2,%3}, {%4,%5,%6,%7}, {%8,%9}, {%0,%1,%2,%3};"
                        : "+f"(acc[mi][2 * p + 1][0]), "+f"(acc[mi][2 * p + 1][1]),
                          "+f"(acc[mi][2 * p + 1][2]), "+f"(acc[mi][2 * p + 1][3])
                        : "r"(ar[mi][0]), "r"(ar[mi][1]), "r"(ar[mi][2]), "r"(ar[mi][3]),
                          "r"(br[p][1]), "r"(br[p][3]));
                }
            }
        }
        st++; if (st >= NST) st = 0;
    }

    // epilogue: bias add + guarded store
#pragma unroll
    for (int mi = 0; mi < 4; mi++) {
        int gr0 = bm * 128 + wm * 64 + mi * 16 + g;
#pragma unroll
        for (int ni = 0; ni < 4; ni++) {
            int gc0 = bn * 128 + wn * 32 + ni * 8 + 2 * t;
            float b0 = (gc0 < VV) ? __ldg(&bias[gc0]) : 0.f;
            float b1 = (gc0 + 1 < VV) ? __ldg(&bias[gc0 + 1]) : 0.f;
            if (gr0 < MM) {
                if (gc0 < VV)     C[(size_t)gr0 * VV + gc0]     = acc[mi][ni][0] + b0;
                if (gc0 + 1 < VV) C[(size_t)gr0 * VV + gc0 + 1] = acc[mi][ni][1] + b1;
            }
            if (gr0 + 8 < MM) {
                if (gc0 < VV)     C[(size_t)(gr0 + 8) * VV + gc0]     = acc[mi][ni][2] + b0;
                if (gc0 + 1 < VV) C[(size_t)(gr0 + 8) * VV + gc0 + 1] = acc[mi][ni][3] + b1;
            }
        }
    }
}

// ---------------------------------------------------------------------------
// K6: in-place log_softmax, float4 + online max/sum
__global__ void k_lsm(float* __restrict__ C) {
    int row = blockIdx.x;
    float4* p4 = (float4*)(C + (size_t)row * VV);   // 1250 float4
    __shared__ float rm[256], rs[256];
    int tid = threadIdx.x;

    float m = -1e30f, s = 0.f;
    for (int i = tid; i < VV / 4; i += 256) {
        float4 v = p4[i];
#pragma unroll
        for (int j = 0; j < 4; j++) {
            float x = (&v.x)[j];
            if (x > m) { s *= __expf(m - x); m = x; }
            s += __expf(x - m);
        }
    }
    rm[tid] = m; rs[tid] = s;
    for (int st = 128; st > 0; st >>= 1) {
        __syncthreads();
        if (tid < st) {
            float m2 = rm[tid + st], s2 = rs[tid + st];
            float M = fmaxf(rm[tid], m2);
            rs[tid] = rs[tid] * __expf(rm[tid] - M) + s2 * __expf(m2 - M);
            rm[tid] = M;
        }
    }
    __syncthreads();
    float lse = rm[0] + logf(rs[0]);

    for (int i = tid; i < VV / 4; i += 256) {
        float4 v = p4[i];
        v.x -= lse; v.y -= lse; v.z -= lse; v.w -= lse;
        p4[i] = v;
    }
}

// ---------------------------------------------------------------------------
extern "C" void kernel_launch(void* const* d_in, const int* in_sizes, int n_in,
                              void* d_out, int out_size) {
    const float* memory = (const float*)d_in[0];
    const int*   ys     = (const int*)d_in[1];
    const float* emb    = (const float*)d_in[3];
    const float* Wih    = (const float*)d_in[4];
    const float* bih    = (const float*)d_in[5];
    const float* Whh    = (const float*)d_in[6];
    const float* bhh    = (const float*)d_in[7];
    const float* Wproj  = (const float*)d_in[8];
    const float* bproj  = (const float*)d_in[9];
    const float* lng    = (const float*)d_in[10];
    const float* lnb    = (const float*)d_in[11];
    const float* Wenc   = (const float*)d_in[12];
    const float* benc   = (const float*)d_in[13];
    const float* Wprd   = (const float*)d_in[14];
    const float* bprd   = (const float*)d_in[15];
    const float* Wout   = (const float*)d_in[16];
    const float* bout   = (const float*)d_in[17];
    float* out = (float*)d_out;

    cudaFuncSetAttribute(k_gemm_hmma, cudaFuncAttributeMaxDynamicSharedMemorySize, GEMM_SMEM);

    k_wconv<<<(VV * NI) / 4 / 256, 256>>>(Wout);
    k_whconvT<<<(4 * DD * DD) / 256, 256>>>(Whh);
    dim3 gx(4, Bq * UU);
    k_gx<<<gx, 256>>>(ys, emb, Wih, bih, bhh);
    k_lstm_r2<<<Bq, 1024>>>();
    dim3 ge(NI / 256, Bq * TT);
    k_enc<<<ge, 256>>>(memory, Wenc, benc);
    k_proj<<<Bq * UU, 256>>>(Wproj, bproj, lng, lnb, Wprd, bprd);
    k_joint<<<(MM * (NI / 4)) / 256, 256>>>();
    dim3 gg((VV + 127) / 128, (MM + 127) / 128);
    k_gemm_hmma<<<gg, 256, GEMM_SMEM>>>(bout, out);
    k_lsm<<<MM, 256>>>(out);
}

// round 8
// speedup vs baseline: 6.1824x; 1.0712x over previous
#include <cuda_runtime.h>
#include <cuda_bf16.h>
#include <cstdint>
#include <math.h>

#define Bq 2
#define TT 200
#define UU 50
#define DD 256
#define NI 2048
#define VV 5000
#define MM (Bq*TT*UU)   /* 20000 */

#define SSTR 40          /* padded smem row stride in bf16 */
#define NST 3            /* gemm pipeline stages */
#define STAGE_ELEMS (128*SSTR)            /* per matrix per stage */
#define GEMM_SMEM (NST*2*STAGE_ELEMS*2)   /* bytes = 61440 */

// LSTM multiblock smem: weights 1024x40 bf16 + floats (shk32, sp1024, sg1024, sc256)
#define LSTM_SW_BYTES (1024*40*2)
#define LSTM_SMEM (LSTM_SW_BYTES + (32+1024+1024+256)*4)

// Scratch (__device__ globals; no allocations anywhere)
__device__ float g_enc[Bq*TT*NI];
__device__ float g_dec[Bq*UU*NI];
__device__ float g_h[Bq*UU*DD];
__device__ float g_gx[Bq*UU*4*DD];                  // precomputed input gates
__device__ __nv_bfloat16 g_whhT[DD*4*DD];           // W_hh^T (k-major) bf16
__device__ __nv_bfloat16 g_jointh[(size_t)MM*NI];   // 82MB bf16
__device__ __nv_bfloat16 g_woutb[(size_t)VV*NI];    // 20MB bf16
// LSTM cross-block state
__device__ float g_part[Bq][8][4*DD];
__device__ float g_hcur[Bq][DD];
__device__ int   g_hflag[Bq];
__device__ int   g_pflag[Bq][8];

__device__ __forceinline__ uint32_t smem_u32(const void* p) {
    uint32_t a;
    asm("{ .reg .u64 t; cvta.to.shared.u64 t, %1; cvt.u32.u64 %0, t; }" : "=r"(a) : "l"(p));
    return a;
}
__device__ __forceinline__ float tanh_fast(float x) {
    float r;
    asm("tanh.approx.f32 %0, %1;" : "=f"(r) : "f"(x));
    return r;
}
__device__ __forceinline__ int ld_acq(const int* p) {
    int v;
    asm volatile("ld.acquire.gpu.global.b32 %0, [%1];" : "=r"(v) : "l"(p));
    return v;
}
__device__ __forceinline__ void st_rel(int* p, int v) {
    asm volatile("st.release.gpu.global.b32 [%0], %1;" :: "l"(p), "r"(v));
}

// ---------------------------------------------------------------------------
// K1: enc = memory @ W_enc^T + b_enc
__global__ void k_enc(const float* __restrict__ mem,
                      const float* __restrict__ W,
                      const float* __restrict__ bias) {
    __shared__ float sx[DD];
    int row = blockIdx.y;
    int j = blockIdx.x * 256 + threadIdx.x;
    sx[threadIdx.x] = mem[row * DD + threadIdx.x];
    __syncthreads();
    const float4* w4 = reinterpret_cast<const float4*>(W + (size_t)j * DD);
    const float4* x4 = reinterpret_cast<const float4*>(sx);
    float acc = bias[j];
#pragma unroll 16
    for (int k = 0; k < DD / 4; k++) {
        float4 w = w4[k], x = x4[k];
        acc += w.x * x.x + w.y * x.y + w.z * x.z + w.w * x.w;
    }
    g_enc[(size_t)row * NI + j] = acc;
}

// ---------------------------------------------------------------------------
// K2a: gx[row, j] = emb[tok[row]] . W_ih[j] + b_ih[j] + b_hh[j]
__global__ void k_gx(const int* __restrict__ tok,
                     const float* __restrict__ emb,
                     const float* __restrict__ Wih, const float* __restrict__ bih,
                     const float* __restrict__ bhh) {
    __shared__ float sx[DD];
    int row = blockIdx.y;                  // b*UU + u
    int j = blockIdx.x * 256 + threadIdx.x;
    if (threadIdx.x < DD) {
        int t = tok[row];
        sx[threadIdx.x] = emb[(size_t)t * DD + threadIdx.x];
    }
    __syncthreads();
    const float4* w4 = (const float4*)(Wih + (size_t)j * DD);
    const float4* x4 = (const float4*)sx;
    float acc = bih[j] + bhh[j];
#pragma unroll 16
    for (int k = 0; k < DD / 4; k++) {
        float4 w = w4[k], x = x4[k];
        acc += w.x * x.x + w.y * x.y + w.z * x.z + w.w * x.w;
    }
    g_gx[(size_t)row * (4 * DD) + j] = acc;
}

// K2b: W_hh -> bf16, transposed to k-major: g_whhT[k*1024 + j] = W[j*256 + k]
__global__ void k_whconvT(const float* __restrict__ W) {
    int idx = blockIdx.x * 256 + threadIdx.x;
    int j = idx >> 8;
    int k = idx & 255;
    g_whhT[k * (4 * DD) + j] = __float2bfloat16(W[idx]);
}

// K2c-pre: zero flags + h state (every replay)
__global__ void k_zero() {
    int tid = threadIdx.x;   // 512 threads, 1 block
    if (tid < Bq) g_hflag[tid] = 0;
    if (tid < Bq * 8) ((int*)g_pflag)[tid] = 0;
    if (tid < Bq * DD) ((float*)g_hcur)[tid] = 0.f;
}

// K2c: multi-block LSTM. grid 16 = (b, slice of 32 k). Weights in smem.
extern __shared__ unsigned char lsm_raw[];
__global__ void __launch_bounds__(1024) k_lstm_mb() {
    const int bx = blockIdx.x;
    const int b = bx >> 3, sl = bx & 7;
    const int tid = threadIdx.x;            // 0..1023 = gate output j
    const int k0 = sl * 32;

    __nv_bfloat16* sw = (__nv_bfloat16*)lsm_raw;              // [1024][40]
    float* shk = (float*)(lsm_raw + LSTM_SW_BYTES);           // [32]
    float* sp  = shk + 32;                                    // [1024]
    float* sg  = sp + 1024;                                   // [1024]
    float* sc  = sg + 1024;                                   // [256]

    // stage weights: sw[j][k] = g_whhT[(k0+k)*1024 + j], coalesced reads
#pragma unroll
    for (int it = 0; it < 32; it++) {
        int j = tid;            // 0..1023
        int k = it;
        sw[j * 40 + k] = g_whhT[(size_t)(k0 + k) * (4 * DD) + j];
    }
    if (tid < DD) sc[tid] = 0.f;
    __syncthreads();

    for (int u = 0; u < UU; u++) {
        // wait for h of step u
        if (tid == 0) {
            while (ld_acq(&g_hflag[b]) < u) { }
        }
        __syncthreads();
        if (tid < 32) shk[tid] = g_hcur[b][k0 + tid];
        __syncthreads();

        // load h slice to regs
        float hr[32];
#pragma unroll
        for (int i = 0; i < 8; i++)
            *(float4*)&hr[4 * i] = *(const float4*)&shk[4 * i];

        // partial dot: j = tid over k slice
        float acc = 0.f;
        const __nv_bfloat16* wrow = sw + tid * 40;
#pragma unroll
        for (int c = 0; c < 4; c++) {
            uint4 q = *(const uint4*)(wrow + c * 8);
            float2 p0 = __bfloat1622float2(*(const __nv_bfloat162*)&q.x);
            float2 p1 = __bfloat1622float2(*(const __nv_bfloat162*)&q.y);
            float2 p2 = __bfloat1622float2(*(const __nv_bfloat162*)&q.z);
            float2 p3 = __bfloat1622float2(*(const __nv_bfloat162*)&q.w);
            acc += p0.x * hr[c * 8 + 0] + p0.y * hr[c * 8 + 1]
                 + p1.x * hr[c * 8 + 2] + p1.y * hr[c * 8 + 3]
                 + p2.x * hr[c * 8 + 4] + p2.y * hr[c * 8 + 5]
                 + p3.x * hr[c * 8 + 6] + p3.y * hr[c * 8 + 7];
        }

        if (sl != 0) {
            g_part[b][sl][tid] = acc;
            __threadfence();
            __syncthreads();
            if (tid == 0) st_rel(&g_pflag[b][sl], u + 1);
        } else {
            sp[tid] = acc;
            __syncthreads();
            // wait for the 7 other slices
            if (tid < 7) {
                while (ld_acq(&g_pflag[b][tid + 1]) < u + 1) { }
            }
            __syncthreads();
            float gacc = g_gx[(size_t)(b * UU + u) * (4 * DD) + tid] + sp[tid];
#pragma unroll
            for (int s = 1; s < 8; s++) gacc += g_part[b][s][tid];
            sg[tid] = gacc;
            __syncthreads();
            if (tid < DD) {
                float ig = 1.f / (1.f + expf(-sg[tid]));
                float fg = 1.f / (1.f + expf(-sg[DD + tid]));
                float gg = tanhf(sg[2 * DD + tid]);
                float og = 1.f / (1.f + expf(-sg[3 * DD + tid]));
                float c = fg * sc[tid] + ig * gg;
                float h = og * tanhf(c);
                sc[tid] = c;
                g_h[(b * UU + u) * DD + tid] = h;
                g_hcur[b][tid] = h;
                __threadfence();
            }
            __syncthreads();
            if (tid == 0) st_rel(&g_hflag[b], u + 1);
        }
    }
}

// ---------------------------------------------------------------------------
// K3: proj + LayerNorm + dec pre-linear
__global__ void k_proj(const float* __restrict__ Wp, const float* __restrict__ bp,
                       const float* __restrict__ lng, const float* __restrict__ lnb,
                       const float* __restrict__ Wprd, const float* __restrict__ bprd) {
    int row = blockIdx.x;
    int tid = threadIdx.x;
    __shared__ float shh[DD], sy[DD], red[256];
    shh[tid] = g_h[row * DD + tid];
    __syncthreads();
    {
        const float4* h4 = (const float4*)shh;
        const float4* w4 = (const float4*)(Wp + (size_t)tid * DD);
        float p = bp[tid];
#pragma unroll 16
        for (int k = 0; k < DD / 4; k++) {
            float4 w = w4[k], h = h4[k];
            p += w.x * h.x + w.y * h.y + w.z * h.z + w.w * h.w;
        }
        red[tid] = p;
        for (int s = 128; s > 0; s >>= 1) { __syncthreads(); if (tid < s) red[tid] += red[tid + s]; }
        __syncthreads();
        float mu = red[0] * (1.f / DD);
        __syncthreads();
        float d = p - mu;
        red[tid] = d * d;
        for (int s = 128; s > 0; s >>= 1) { __syncthreads(); if (tid < s) red[tid] += red[tid + s]; }
        __syncthreads();
        float var = red[0] * (1.f / DD);
        float y = d * rsqrtf(var + 1e-5f) * lng[tid] + lnb[tid];
        sy[tid] = y;
    }
    __syncthreads();
    const float4* y4 = (const float4*)sy;
    for (int j = tid; j < NI; j += 256) {
        const float4* w4 = (const float4*)(Wprd + (size_t)j * DD);
        float acc = bprd[j];
#pragma unroll 16
        for (int k = 0; k < DD / 4; k++) {
            float4 w = w4[k], y = y4[k];
            acc += w.x * y.x + w.y * y.y + w.z * y.z + w.w * y.w;
        }
        g_dec[row * NI + j] = acc;
    }
}

// ---------------------------------------------------------------------------
// K4: joint = tanh(enc + dec) -> bf16 (MUFU tanh)
__global__ void k_joint() {
    int idx = blockIdx.x * 256 + threadIdx.x;       // float4 index
    int r = idx / (NI / 4);
    int k = (idx % (NI / 4)) * 4;
    int b = r / (TT * UU);
    int rem = r % (TT * UU);
    int t = rem / UU;
    int u = rem % UU;
    float4 e = *(const float4*)&g_enc[(size_t)(b * TT + t) * NI + k];
    float4 d = *(const float4*)&g_dec[(size_t)(b * UU + u) * NI + k];
    __nv_bfloat162 lo = __floats2bfloat162_rn(tanh_fast(e.x + d.x), tanh_fast(e.y + d.y));
    __nv_bfloat162 hi = __floats2bfloat162_rn(tanh_fast(e.z + d.z), tanh_fast(e.w + d.w));
    uint2 pk;
    pk.x = *(uint32_t*)&lo;
    pk.y = *(uint32_t*)&hi;
    *(uint2*)&g_jointh[(size_t)r * NI + k] = pk;
}

// ---------------------------------------------------------------------------
// K4b: W_out -> bf16
__global__ void k_wconv(const float* __restrict__ W) {
    size_t i = ((size_t)blockIdx.x * 256 + threadIdx.x) * 4;
    float4 v = *(const float4*)(W + i);
    __nv_bfloat162 lo = __floats2bfloat162_rn(v.x, v.y);
    __nv_bfloat162 hi = __floats2bfloat162_rn(v.z, v.w);
    uint2 pk;
    pk.x = *(uint32_t*)&lo;
    pk.y = *(uint32_t*)&hi;
    *(uint2*)&g_woutb[i] = pk;
}

// ---------------------------------------------------------------------------
// K5: logits = joint @ W_out^T + b_out via mma.sync bf16 + ldmatrix
// 128x128x32 CTA tile, 4 warps (2x2), warp = 64x64, 3-stage cp.async pipeline
#define NIT (NI/32)   /* 64 */

__device__ __forceinline__ void cp16(uint32_t dst, const void* src, int sz) {
    asm volatile("cp.async.cg.shared.global [%0], [%1], 16, %2;"
                 :: "r"(dst), "l"(src), "r"(sz));
}

#define LDM_X4(r0, r1, r2, r3, a) \
    asm volatile("ldmatrix.sync.aligned.m8n8.x4.shared.b16 {%0,%1,%2,%3}, [%4];" \
                 : "=r"(r0), "=r"(r1), "=r"(r2), "=r"(r3) : "r"(a))

extern __shared__ __nv_bfloat16 dsm[];   // NST stages: [A(128*SSTR) | B(128*SSTR)]

__global__ void __launch_bounds__(128, 2) k_gemm_hmma(const float* __restrict__ bias,
                                                      float* __restrict__ C) {
    const int tid = threadIdx.x;
    const int wid = tid >> 5, lid = tid & 31;
    const int wm = wid >> 1, wn = wid & 1;       // warp grid 2x2, warp tile 64x64
    const int g = lid >> 2, t = lid & 3;         // mma lane decomposition
    const int bm = blockIdx.y, bn = blockIdx.x;

    // ldmatrix per-lane tile offsets (elements)
    const int lq = lid >> 3, lr_ = lid & 7;
    const int ld_row = ((lq & 1) << 3) + lr_;    // 0..15
    const int ld_col = (lq >> 1) << 3;           // 0 or 8
    int aoff[4], boff[4];
#pragma unroll
    for (int mi = 0; mi < 4; mi++)
        aoff[mi] = (wm * 64 + mi * 16 + ld_row) * SSTR + ld_col;
#pragma unroll
    for (int p = 0; p < 4; p++)
        boff[p] = (wn * 64 + p * 16 + ld_row) * SSTR + ld_col;

    uint32_t sbase[NST];
#pragma unroll
    for (int s = 0; s < NST; s++) sbase[s] = smem_u32(dsm + s * 2 * STAGE_ELEMS);

    const int r_ = tid >> 2;            // 0..31 (rows r_, r_+32, r_+64, r_+96)
    const int ch = tid & 3;             // 16B chunk within 64B row

    const __nv_bfloat16* srcA[4];
    const __nv_bfloat16* srcB[4];
    int szA[4], szB[4];
    uint32_t dA[4], dB[4];
#pragma unroll
    for (int i = 0; i < 4; i++) {
        int rowi = r_ + 32 * i;
        int ra = bm * 128 + rowi, rb = bn * 128 + rowi;
        srcA[i] = g_jointh + (size_t)(ra < MM ? ra : MM - 1) * NI + ch * 8;
        srcB[i] = g_woutb + (size_t)(rb < VV ? rb : VV - 1) * NI + ch * 8;
        szA[i] = ra < MM ? 16 : 0;
        szB[i] = rb < VV ? 16 : 0;
        dA[i] = (rowi * SSTR + ch * 8) * 2;
        dB[i] = dA[i] + STAGE_ELEMS * 2;
    }

#define LOAD_STAGE(s, it) do { \
    int ck = (it) * 32; \
    uint32_t sb = sbase[s]; \
    cp16(sb + dA[0], srcA[0] + ck, szA[0]); \
    cp16(sb + dA[1], srcA[1] + ck, szA[1]); \
    cp16(sb + dA[2], srcA[2] + ck, szA[2]); \
    cp16(sb + dA[3], srcA[3] + ck, szA[3]); \
    cp16(sb + dB[0], srcB[0] + ck, szB[0]); \
    cp16(sb + dB[1], srcB[1] + ck, szB[1]); \
    cp16(sb + dB[2], srcB[2] + ck, szB[2]); \
    cp16(sb + dB[3], srcB[3] + ck, szB[3]); \
} while (0)

    float acc[4][8][4];
#pragma unroll
    for (int i = 0; i < 4; i++)
#pragma unroll
        for (int j = 0; j < 8; j++)
#pragma unroll
            for (int k = 0; k < 4; k++) acc[i][j][k] = 0.f;

    // prologue
    LOAD_STAGE(0, 0);
    asm volatile("cp.async.commit_group;");
    LOAD_STAGE(1, 1);
    asm volatile("cp.async.commit_group;");

    int st = 0;
    for (int it = 0; it < NIT; it++) {
        asm volatile("cp.async.wait_group 1;");
        __syncthreads();
        if (it + 2 < NIT) {
            int s2 = st + 2; if (s2 >= NST) s2 -= NST;
            LOAD_STAGE(s2, it + 2);
        }
        asm volatile("cp.async.commit_group;");

        const uint32_t asb = sbase[st];
        const uint32_t bsb = asb + STAGE_ELEMS * 2;
#pragma unroll
        for (int ks = 0; ks < 2; ks++) {
            const int kk = ks * 16;
            uint32_t ar[4][4], br[4][4];
#pragma unroll
            for (int mi = 0; mi < 4; mi++)
                LDM_X4(ar[mi][0], ar[mi][1], ar[mi][2], ar[mi][3],
                       asb + ((aoff[mi] + kk) << 1));
#pragma unroll
            for (int p = 0; p < 4; p++)
                LDM_X4(br[p][0], br[p][1], br[p][2], br[p][3],
                       bsb + ((boff[p] + kk) << 1));
#pragma unroll
            for (int mi = 0; mi < 4; mi++) {
#pragma unroll
                for (int p = 0; p < 4; p++) {
                    asm volatile(
                        "mma.sync.aligned.m16n8k16.row.col.f32.bf16.bf16.f32 "
                        "{%0,%1,%2,%3}, {%4,%5,%6,%7}, {%8,%9}, {%0,%1,%2,%3};"
                        : "+f"(acc[mi][2 * p][0]), "+f"(acc[mi][2 * p][1]),
                          "+f"(acc[mi][2 * p][2]), "+f"(acc[mi][2 * p][3])
                        : "r"(ar[mi][0]), "r"(ar[mi][1]), "r"(ar[mi][2]), "r"(ar[mi][3]),
                          "r"(br[p][0]), "r"(br[p][2]));
                    asm volatile(
                        "mma.sync.aligned.m16n8k16.row.col.f32.bf16.bf16.f32 "
                        "{%0,%1,%2,%3}, {%4,%5,%6,%7}, {%8,%9}, {%0,%1,%2,%3};"
                        : "+f"(acc[mi][2 * p + 1][0]), "+f"(acc[mi][2 * p + 1][1]),
                          "+f"(acc[mi][2 * p + 1][2]), "+f"(acc[mi][2 * p + 1][3])
                        : "r"(ar[mi][0]), "r"(ar[mi][1]), "r"(ar[mi][2]), "r"(ar[mi][3]),
                          "r"(br[p][1]), "r"(br[p][3]));
                }
            }
        }
        st++; if (st >= NST) st = 0;
    }

    // epilogue: bias add + guarded store
#pragma unroll
    for (int mi = 0; mi < 4; mi++) {
        int gr0 = bm * 128 + wm * 64 + mi * 16 + g;
#pragma unroll
        for (int ni = 0; ni < 8; ni++) {
            int gc0 = bn * 128 + wn * 64 + ni * 8 + 2 * t;
            float b0 = (gc0 < VV) ? __ldg(&bias[gc0]) : 0.f;
            float b1 = (gc0 + 1 < VV) ? __ldg(&bias[gc0 + 1]) : 0.f;
            if (gr0 < MM) {
                if (gc0 < VV)     C[(size_t)gr0 * VV + gc0]     = acc[mi][ni][0] + b0;
                if (gc0 + 1 < VV) C[(size_t)gr0 * VV + gc0 + 1] = acc[mi][ni][1] + b1;
            }
            if (gr0 + 8 < MM) {
                if (gc0 < VV)     C[(size_t)(gr0 + 8) * VV + gc0]     = acc[mi][ni][2] + b0;
                if (gc0 + 1 < VV) C[(size_t)(gr0 + 8) * VV + gc0 + 1] = acc[mi][ni][3] + b1;
            }
        }
    }
}

// ---------------------------------------------------------------------------
// K6: in-place log_softmax, float4 + online max/sum
__global__ void k_lsm(float* __restrict__ C) {
    int row = blockIdx.x;
    float4* p4 = (float4*)(C + (size_t)row * VV);   // 1250 float4
    __shared__ float rm[256], rs[256];
    int tid = threadIdx.x;

    float m = -1e30f, s = 0.f;
    for (int i = tid; i < VV / 4; i += 256) {
        float4 v = p4[i];
#pragma unroll
        for (int j = 0; j < 4; j++) {
            float x = (&v.x)[j];
            if (x > m) { s *= __expf(m - x); m = x; }
            s += __expf(x - m);
        }
    }
    rm[tid] = m; rs[tid] = s;
    for (int st = 128; st > 0; st >>= 1) {
        __syncthreads();
        if (tid < st) {
            float m2 = rm[tid + st], s2 = rs[tid + st];
            float M = fmaxf(rm[tid], m2);
            rs[tid] = rs[tid] * __expf(rm[tid] - M) + s2 * __expf(m2 - M);
            rm[tid] = M;
        }
    }
    __syncthreads();
    float lse = rm[0] + logf(rs[0]);

    for (int i = tid; i < VV / 4; i += 256) {
        float4 v = p4[i];
        v.x -= lse; v.y -= lse; v.z -= lse; v.w -= lse;
        p4[i] = v;
    }
}

// ---------------------------------------------------------------------------
extern "C" void kernel_launch(void* const* d_in, const int* in_sizes, int n_in,
                              void* d_out, int out_size) {
    const float* memory = (const float*)d_in[0];
    const int*   ys     = (const int*)d_in[1];
    const float* emb    = (const float*)d_in[3];
    const float* Wih    = (const float*)d_in[4];
    const float* bih    = (const float*)d_in[5];
    const float* Whh    = (const float*)d_in[6];
    const float* bhh    = (const float*)d_in[7];
    const float* Wproj  = (const float*)d_in[8];
    const float* bproj  = (const float*)d_in[9];
    const float* lng    = (const float*)d_in[10];
    const float* lnb    = (const float*)d_in[11];
    const float* Wenc   = (const float*)d_in[12];
    const float* benc   = (const float*)d_in[13];
    const float* Wprd   = (const float*)d_in[14];
    const float* bprd   = (const float*)d_in[15];
    const float* Wout   = (const float*)d_in[16];
    const float* bout   = (const float*)d_in[17];
    float* out = (float*)d_out;

    cudaFuncSetAttribute(k_gemm_hmma, cudaFuncAttributeMaxDynamicSharedMemorySize, GEMM_SMEM);
    cudaFuncSetAttribute(k_lstm_mb, cudaFuncAttributeMaxDynamicSharedMemorySize, LSTM_SMEM);

    k_wconv<<<(VV * NI) / 4 / 256, 256>>>(Wout);
    k_whconvT<<<(4 * DD * DD) / 256, 256>>>(Whh);
    dim3 gx(4, Bq * UU);
    k_gx<<<gx, 256>>>(ys, emb, Wih, bih, bhh);
    k_zero<<<1, 512>>>();
    k_lstm_mb<<<Bq * 8, 1024, LSTM_SMEM>>>();
    dim3 ge(NI / 256, Bq * TT);
    k_enc<<<ge, 256>>>(memory, Wenc, benc);
    k_proj<<<Bq * UU, 256>>>(Wproj, bproj, lng, lnb, Wprd, bprd);
    k_joint<<<(MM * (NI / 4)) / 256, 256>>>();
    dim3 gg((VV + 127) / 128, (MM + 127) / 128);
    k_gemm_hmma<<<gg, 128, GEMM_SMEM>>>(bout, out);
    k_lsm<<<MM, 256>>>(out);
}